// round 1
// baseline (speedup 1.0000x reference)
#include <cuda_runtime.h>

#define NN 50000
#define EE 800000
#define DD 128
#define NEV 4
#define EPSV 1e-8f

// ---------------- scratch (device globals; no allocation allowed) ----------------
__device__ float d_h[(size_t)NN * NEV * DD];   // [n][e][f]  102.4 MB
__device__ float d_ssrc[NN * NEV];             // [n][e]
__device__ float d_sdst[NN * NEV];             // [n][e]
__device__ unsigned d_maxu[NEV];               // ordered-uint encoded per-env max
__device__ int d_cnt[NN];
__device__ int d_off[NN + 1];
__device__ int d_cur[NN];
__device__ int d_csr[EE];                      // dst ids grouped by src

__device__ __forceinline__ unsigned fenc(float f) {
    unsigned u = __float_as_uint(f);
    return (u & 0x80000000u) ? ~u : (u | 0x80000000u);
}
__device__ __forceinline__ float fdec(unsigned u) {
    u = (u & 0x80000000u) ? (u & 0x7fffffffu) : ~u;
    return __uint_as_float(u);
}
__device__ __forceinline__ float lrelu(float v) { return v > 0.f ? v : 0.01f * v; }

// ---------------- init: zero histogram + max ----------------
__global__ void init_kernel() {
    int i = blockIdx.x * blockDim.x + threadIdx.x;
    if (i < NN) d_cnt[i] = 0;
    if (i < NEV) d_maxu[i] = 0u;
}

// ---------------- GEMM: h[n][e][:] = x[n,:] @ W_e  (BM=64, BK=32, BN=128) ----------------
__global__ void gemm_kernel(const float* __restrict__ x, const float* __restrict__ W) {
    __shared__ float Ws[32][DD];   // [kk][f] 16KB
    __shared__ float Xs[64][32];   // [r][kk]  8KB

    int e  = blockIdx.y;
    int n0 = blockIdx.x * 64;
    int t  = threadIdx.x;          // 256 threads
    int rows = NN - n0; if (rows > 64) rows = 64;

    int r0 = (t >> 5) * 8;
    int c0 = (t & 31) * 4;

    float4 acc[8];
#pragma unroll
    for (int r = 0; r < 8; r++) acc[r] = make_float4(0.f, 0.f, 0.f, 0.f);

    const float* Wg = W + (size_t)e * DD * DD;

    for (int k0 = 0; k0 < DD; k0 += 32) {
        // load W tile: 32x128 floats = 1024 float4, 4 per thread
        {
            float4* Ws4 = (float4*)Ws;
            const float4* src = (const float4*)(Wg + (size_t)k0 * DD);
#pragma unroll
            for (int i = 0; i < 4; i++) Ws4[i * 256 + t] = src[i * 256 + t];
        }
        // load X tile: 64x32 floats = 512 float4, 2 per thread
        {
#pragma unroll
            for (int i = 0; i < 2; i++) {
                int q = i * 256 + t;
                int r = q >> 3;
                int kk = (q & 7) * 4;
                float4 v = make_float4(0.f, 0.f, 0.f, 0.f);
                if (r < rows) v = *(const float4*)(x + (size_t)(n0 + r) * DD + k0 + kk);
                *(float4*)&Xs[r][kk] = v;
            }
        }
        __syncthreads();

#pragma unroll
        for (int kk = 0; kk < 32; kk++) {
            float4 w4 = *(const float4*)&Ws[kk][c0];
#pragma unroll
            for (int r = 0; r < 8; r++) {
                float xv = Xs[r0 + r][kk];
                acc[r].x += xv * w4.x;
                acc[r].y += xv * w4.y;
                acc[r].z += xv * w4.z;
                acc[r].w += xv * w4.w;
            }
        }
        __syncthreads();
    }

#pragma unroll
    for (int r = 0; r < 8; r++) {
        int n = n0 + r0 + r;
        if (n < NN) *(float4*)&d_h[((size_t)n * NEV + e) * DD + c0] = acc[r];
    }
}

// ---------------- s projections: s_src[n][e] = h[n][e]·a1[e], s_dst = ·a2[e] ----------------
__global__ void s_kernel(const float* __restrict__ a) {
    int wid  = (blockIdx.x * blockDim.x + threadIdx.x) >> 5;
    int lane = threadIdx.x & 31;
    if (wid >= NN) return;

    float p1[NEV], p2[NEV];
#pragma unroll
    for (int e = 0; e < NEV; e++) {
        float4 h4  = *(const float4*)&d_h[((size_t)wid * NEV + e) * DD + lane * 4];
        float4 a14 = *(const float4*)&a[e * 2 * DD + lane * 4];
        float4 a24 = *(const float4*)&a[e * 2 * DD + DD + lane * 4];
        p1[e] = h4.x * a14.x + h4.y * a14.y + h4.z * a14.z + h4.w * a14.w;
        p2[e] = h4.x * a24.x + h4.y * a24.y + h4.z * a24.z + h4.w * a24.w;
    }
#pragma unroll
    for (int o = 16; o > 0; o >>= 1) {
#pragma unroll
        for (int e = 0; e < NEV; e++) {
            p1[e] += __shfl_xor_sync(0xffffffffu, p1[e], o);
            p2[e] += __shfl_xor_sync(0xffffffffu, p2[e], o);
        }
    }
    if (lane == 0) {
#pragma unroll
        for (int e = 0; e < NEV; e++) {
            d_ssrc[wid * NEV + e] = p1[e];
            d_sdst[wid * NEV + e] = p2[e];
        }
    }
}

// ---------------- histogram of src degrees ----------------
__global__ void hist_kernel(const int* __restrict__ adj) {
    int i = blockIdx.x * blockDim.x + threadIdx.x;
    if (i < EE) atomicAdd(&d_cnt[adj[i]], 1);
}

// ---------------- single-block exclusive scan (1024 threads) ----------------
__global__ void scan_kernel() {
    __shared__ int warp_sums[32];
    __shared__ int s_carry;
    int t = threadIdx.x, lane = t & 31, w = t >> 5;
    if (t == 0) s_carry = 0;
    __syncthreads();

    for (int base = 0; base < NN; base += 1024) {
        int i = base + t;
        int v = (i < NN) ? d_cnt[i] : 0;
        int s = v;
#pragma unroll
        for (int o = 1; o < 32; o <<= 1) {
            int y = __shfl_up_sync(0xffffffffu, s, o);
            if (lane >= o) s += y;
        }
        if (lane == 31) warp_sums[w] = s;
        __syncthreads();
        if (w == 0) {
            int ws = warp_sums[lane];
#pragma unroll
            for (int o = 1; o < 32; o <<= 1) {
                int y = __shfl_up_sync(0xffffffffu, ws, o);
                if (lane >= o) ws += y;
            }
            warp_sums[lane] = ws;
        }
        __syncthreads();
        int pre = s_carry + (w ? warp_sums[w - 1] : 0) + s - v;  // exclusive
        int tot = warp_sums[31];
        if (i < NN) { d_off[i] = pre; d_cur[i] = pre; }
        __syncthreads();
        if (t == 0) s_carry += tot;
        __syncthreads();
    }
    if (t == 0) d_off[NN] = s_carry;
}

// ---------------- scatter edges into CSR groups ----------------
__global__ void scatter_kernel(const int* __restrict__ adj) {
    int i = blockIdx.x * blockDim.x + threadIdx.x;
    if (i < EE) {
        int r = adj[i];
        int c = adj[EE + i];
        int p = atomicAdd(&d_cur[r], 1);
        d_csr[p] = c;
    }
}

// ---------------- global per-env max of leaky_relu(logits), incl. self loops ----------------
__global__ void max_kernel(const int* __restrict__ adj) {
    const int tot = EE + NN;
    float lm[NEV];
#pragma unroll
    for (int e = 0; e < NEV; e++) lm[e] = -1e30f;

    int stride = gridDim.x * blockDim.x;
    for (int i = blockIdx.x * blockDim.x + threadIdx.x; i < tot; i += stride) {
        int s, d;
        if (i < EE) { s = adj[i]; d = adj[EE + i]; }
        else        { s = i - EE; d = s; }
#pragma unroll
        for (int e = 0; e < NEV; e++) {
            float v = lrelu(d_ssrc[s * NEV + e] + d_sdst[d * NEV + e]);
            lm[e] = fmaxf(lm[e], v);
        }
    }
#pragma unroll
    for (int o = 16; o > 0; o >>= 1)
#pragma unroll
        for (int e = 0; e < NEV; e++)
            lm[e] = fmaxf(lm[e], __shfl_xor_sync(0xffffffffu, lm[e], o));

    __shared__ float red[NEV][8];
    int lane = threadIdx.x & 31, wrp = threadIdx.x >> 5;
    if (lane == 0)
#pragma unroll
        for (int e = 0; e < NEV; e++) red[e][wrp] = lm[e];
    __syncthreads();
    if (wrp == 0) {
#pragma unroll
        for (int e = 0; e < NEV; e++) {
            float v = (lane < 8) ? red[e][lane] : -1e30f;
#pragma unroll
            for (int o = 4; o > 0; o >>= 1)
                v = fmaxf(v, __shfl_xor_sync(0xffffffffu, v, o));
            if (lane == 0) atomicMax(&d_maxu[e], fenc(v));
        }
    }
}

// ---------------- aggregate: one warp per node, fused final combine ----------------
__global__ void agg_kernel(const float* __restrict__ x,
                           const float* __restrict__ envw,
                           float* __restrict__ out) {
    int wid  = (blockIdx.x * blockDim.x + threadIdx.x) >> 5;
    int lane = threadIdx.x & 31;
    if (wid >= NN) return;
    int n = wid;

    float m[NEV], ss[NEV];
#pragma unroll
    for (int e = 0; e < NEV; e++) {
        m[e]  = fdec(d_maxu[e]);
        ss[e] = d_ssrc[n * NEV + e];
    }
    float4 sdn = *(const float4*)&d_sdst[n * NEV];
    float sdv[NEV] = {sdn.x, sdn.y, sdn.z, sdn.w};

    float acc[NEV][4];
    float den[NEV];

    // self loop
#pragma unroll
    for (int e = 0; e < NEV; e++) {
        float wv = __expf(lrelu(ss[e] + sdv[e]) - m[e]);
        den[e] = wv;
        float4 h4 = *(const float4*)&d_h[((size_t)n * NEV + e) * DD + lane * 4];
        acc[e][0] = wv * h4.x; acc[e][1] = wv * h4.y;
        acc[e][2] = wv * h4.z; acc[e][3] = wv * h4.w;
    }

    int start = d_off[n], end = d_off[n + 1];
    int e_l = lane & 3, j_l = lane >> 2;
    float ss_l = ss[e_l], m_l = m[e_l];

    for (int base = start; base < end; base += 8) {
        int idx = base + j_l;
        int dl = 0;
        float wl = 0.f;
        if (idx < end) {
            dl = d_csr[idx];
            float sv = d_sdst[dl * NEV + e_l];
            wl = __expf(lrelu(ss_l + sv) - m_l);
        }
        int cnt = end - base; if (cnt > 8) cnt = 8;
#pragma unroll
        for (int j = 0; j < 8; j++) {
            if (j >= cnt) break;
            int d = __shfl_sync(0xffffffffu, dl, j * 4);
            const float* hp = d_h + (size_t)d * NEV * DD + lane * 4;
#pragma unroll
            for (int e = 0; e < NEV; e++) {
                float wv = __shfl_sync(0xffffffffu, wl, j * 4 + e);
                float4 h4 = *(const float4*)(hp + e * DD);
                den[e] += wv;
                acc[e][0] += wv * h4.x; acc[e][1] += wv * h4.y;
                acc[e][2] += wv * h4.z; acc[e][3] += wv * h4.w;
            }
        }
    }

    float4 ew = *(const float4*)&envw[n * NEV];
    float ewv[NEV] = {ew.x, ew.y, ew.z, ew.w};
    float4 xv = *(const float4*)&x[(size_t)n * DD + lane * 4];
    float o0 = xv.x, o1 = xv.y, o2 = xv.z, o3 = xv.w;
#pragma unroll
    for (int e = 0; e < NEV; e++) {
        float c = ewv[e] / (den[e] + EPSV);
        o0 += c * acc[e][0]; o1 += c * acc[e][1];
        o2 += c * acc[e][2]; o3 += c * acc[e][3];
    }
    *(float4*)&out[(size_t)n * DD + lane * 4] = make_float4(o0, o1, o2, o3);
}

// ---------------- launcher ----------------
extern "C" void kernel_launch(void* const* d_in, const int* in_sizes, int n_in,
                              void* d_out, int out_size) {
    const float* x    = (const float*)d_in[0];
    const int*   adj  = (const int*)d_in[1];
    const float* envw = (const float*)d_in[2];
    const float* W    = (const float*)d_in[3];
    const float* a    = (const float*)d_in[4];
    float* out = (float*)d_out;

    init_kernel<<<(NN + 255) / 256, 256>>>();
    gemm_kernel<<<dim3((NN + 63) / 64, NEV), 256>>>(x, W);
    s_kernel<<<(NN * 32 + 255) / 256, 256>>>(a);
    hist_kernel<<<(EE + 255) / 256, 256>>>(adj);
    scan_kernel<<<1, 1024>>>();
    scatter_kernel<<<(EE + 255) / 256, 256>>>(adj);
    max_kernel<<<1024, 256>>>(adj);
    agg_kernel<<<(NN + 7) / 8, 256>>>(x, envw, out);
}

// round 3
// speedup vs baseline: 1.1394x; 1.1394x over previous
#include <cuda_runtime.h>
#include <cuda_bf16.h>
#include <cstdint>

#define NN 50000
#define EE 800000
#define DD 128
#define NEV 4
#define EPSV 1e-8f

// ---------------- scratch (device globals; no allocation allowed) ----------------
__device__ float d_h[(size_t)NN * NEV * DD];   // [n][e][f]  102.4 MB
__device__ float d_ssrc[NN * NEV];
__device__ float d_sdst[NN * NEV];
__device__ unsigned d_maxu[NEV];
__device__ int d_cnt[NN];
__device__ int d_off[NN + 1];
__device__ int d_cur[NN];
__device__ int d_csr[EE];
__device__ __nv_bfloat16 d_Wth[NEV * DD * DD];   // W^T hi: [e][f][k]
__device__ __nv_bfloat16 d_Wtl[NEV * DD * DD];   // W^T lo

__device__ __forceinline__ unsigned fenc(float f) {
    unsigned u = __float_as_uint(f);
    return (u & 0x80000000u) ? ~u : (u | 0x80000000u);
}
__device__ __forceinline__ float fdec(unsigned u) {
    u = (u & 0x80000000u) ? (u & 0x7fffffffu) : ~u;
    return __uint_as_float(u);
}
__device__ __forceinline__ float lrelu(float v) { return v > 0.f ? v : 0.01f * v; }

__device__ __forceinline__ uint32_t pack_bf2(float lo, float hi) {
    __nv_bfloat162 p;
    p.x = __float2bfloat16(lo);
    p.y = __float2bfloat16(hi);
    return *(uint32_t*)&p;
}

__device__ __forceinline__ void mma_bf16(float& c0, float& c1, float& c2, float& c3,
                                         uint32_t a0, uint32_t a1, uint32_t a2, uint32_t a3,
                                         uint32_t b0, uint32_t b1) {
    asm volatile(
        "mma.sync.aligned.m16n8k16.row.col.f32.bf16.bf16.f32 "
        "{%0,%1,%2,%3}, {%4,%5,%6,%7}, {%8,%9}, {%0,%1,%2,%3};\n"
        : "+f"(c0), "+f"(c1), "+f"(c2), "+f"(c3)
        : "r"(a0), "r"(a1), "r"(a2), "r"(a3), "r"(b0), "r"(b1));
}

// smem layout (word offsets). Row stride 68 words: bank(row,kw) = (4*row + kw) % 32
#define ROWW 68
#define AH_W 0
#define AL_W (128 * ROWW)
#define BH_W (2 * 128 * ROWW)
#define BL_W (3 * 128 * ROWW)
#define SRED_W (4 * 128 * ROWW)               // 256 floats (s1[128], s2[128])
#define SMEM_WORDS (SRED_W + 256)
#define SMEM_BYTES (SMEM_WORDS * 4)

// ---------------- init ----------------
__global__ void init_kernel() {
    int i = blockIdx.x * blockDim.x + threadIdx.x;
    if (i < NN) d_cnt[i] = 0;
    if (i < NEV) d_maxu[i] = 0u;
}

// ---------------- prep: W^T split into bf16 hi/lo ----------------
__global__ void wprep_kernel(const float* __restrict__ W) {
    int i = blockIdx.x * blockDim.x + threadIdx.x;   // 4*128*128 = 65536
    if (i >= NEV * DD * DD) return;
    int e = i >> 14;
    int k = (i >> 7) & 127;
    int f = i & 127;
    float v = W[i];
    __nv_bfloat16 hb = __float2bfloat16(v);
    __nv_bfloat16 lb = __float2bfloat16(v - __bfloat162float(hb));
    int o = ((e * DD + f) << 7) + k;
    d_Wth[o] = hb;
    d_Wtl[o] = lb;
}

// ---------------- GEMM: h = x @ W_e via mma.sync bf16x3, fused s projections ----------------
__global__ void __launch_bounds__(256) gemm_kernel(const float* __restrict__ x,
                                                   const float* __restrict__ a) {
    extern __shared__ uint32_t sm[];
    int t = threadIdx.x, lane = t & 31, wid = t >> 5;
    int e = blockIdx.y;
    int n0 = blockIdx.x * 128;

    float* s1r = (float*)(sm + SRED_W);
    float* s2r = s1r + 128;
    if (t < 128) { s1r[t] = 0.f; s2r[t] = 0.f; }

    // ---- fill A (x tile, split hi/lo) ----
    const float4* x4 = (const float4*)x;
#pragma unroll
    for (int i = 0; i < 16; i++) {
        int q = i * 256 + t;
        int row = q >> 5;
        int c4 = q & 31;
        float4 v = make_float4(0.f, 0.f, 0.f, 0.f);
        int n = n0 + row;
        if (n < NN) v = x4[(size_t)n * 32 + c4];
        float h0 = __bfloat162float(__float2bfloat16(v.x));
        float h1 = __bfloat162float(__float2bfloat16(v.y));
        float h2 = __bfloat162float(__float2bfloat16(v.z));
        float h3 = __bfloat162float(__float2bfloat16(v.w));
        uint2 hv, lv;
        hv.x = pack_bf2(v.x, v.y); hv.y = pack_bf2(v.z, v.w);
        lv.x = pack_bf2(v.x - h0, v.y - h1); lv.y = pack_bf2(v.z - h2, v.w - h3);
        *(uint2*)(sm + AH_W + row * ROWW + 2 * c4) = hv;
        *(uint2*)(sm + AL_W + row * ROWW + 2 * c4) = lv;
    }

    // ---- fill B (pre-transposed W^T rows, coalesced copy) ----
    const uint2* wh2 = (const uint2*)(d_Wth + e * DD * DD);
    const uint2* wl2 = (const uint2*)(d_Wtl + e * DD * DD);
#pragma unroll
    for (int i = 0; i < 16; i++) {
        int q = i * 256 + t;
        int row = q >> 5;          // f
        int kq = q & 31;           // uint2 = 4 bf16 = 2 words
        *(uint2*)(sm + BH_W + row * ROWW + 2 * kq) = wh2[row * 32 + kq];
        *(uint2*)(sm + BL_W + row * ROWW + 2 * kq) = wl2[row * 32 + kq];
    }
    __syncthreads();

    // ---- mma mainloop ----
    int warpM = (wid >> 1) * 32;       // 0,32,64,96
    int warpN = (wid & 1) * 64;        // 0,64
    int g = lane >> 2, th = lane & 3;

    float acc[2][8][4];
#pragma unroll
    for (int mt = 0; mt < 2; mt++)
#pragma unroll
        for (int nt = 0; nt < 8; nt++)
#pragma unroll
            for (int j = 0; j < 4; j++) acc[mt][nt][j] = 0.f;

#pragma unroll
    for (int kk = 0; kk < 8; kk++) {
        uint32_t ah[2][4], al[2][4];
#pragma unroll
        for (int mt = 0; mt < 2; mt++) {
            int r0 = warpM + mt * 16 + g;
            int kb = kk * 8 + th;
            ah[mt][0] = sm[AH_W + r0 * ROWW + kb];
            ah[mt][1] = sm[AH_W + (r0 + 8) * ROWW + kb];
            ah[mt][2] = sm[AH_W + r0 * ROWW + kb + 4];
            ah[mt][3] = sm[AH_W + (r0 + 8) * ROWW + kb + 4];
            al[mt][0] = sm[AL_W + r0 * ROWW + kb];
            al[mt][1] = sm[AL_W + (r0 + 8) * ROWW + kb];
            al[mt][2] = sm[AL_W + r0 * ROWW + kb + 4];
            al[mt][3] = sm[AL_W + (r0 + 8) * ROWW + kb + 4];
        }
#pragma unroll
        for (int nt = 0; nt < 8; nt++) {
            int nIdx = warpN + nt * 8 + g;
            int kb = kk * 8 + th;
            uint32_t bh0 = sm[BH_W + nIdx * ROWW + kb];
            uint32_t bh1 = sm[BH_W + nIdx * ROWW + kb + 4];
            uint32_t bl0 = sm[BL_W + nIdx * ROWW + kb];
            uint32_t bl1 = sm[BL_W + nIdx * ROWW + kb + 4];
#pragma unroll
            for (int mt = 0; mt < 2; mt++) {
                mma_bf16(acc[mt][nt][0], acc[mt][nt][1], acc[mt][nt][2], acc[mt][nt][3],
                         ah[mt][0], ah[mt][1], ah[mt][2], ah[mt][3], bh0, bh1);
                mma_bf16(acc[mt][nt][0], acc[mt][nt][1], acc[mt][nt][2], acc[mt][nt][3],
                         ah[mt][0], ah[mt][1], ah[mt][2], ah[mt][3], bl0, bl1);
                mma_bf16(acc[mt][nt][0], acc[mt][nt][1], acc[mt][nt][2], acc[mt][nt][3],
                         al[mt][0], al[mt][1], al[mt][2], al[mt][3], bh0, bh1);
            }
        }
    }

    // ---- epilogue: write h + fused s projections ----
    const float* a1 = a + e * 2 * DD;
    const float* a2 = a1 + DD;
#pragma unroll
    for (int mt = 0; mt < 2; mt++) {
#pragma unroll
        for (int half = 0; half < 2; half++) {
            int row_local = warpM + mt * 16 + half * 8 + g;
            int n = n0 + row_local;
            float p1 = 0.f, p2 = 0.f;
#pragma unroll
            for (int nt = 0; nt < 8; nt++) {
                int col = warpN + nt * 8 + 2 * th;
                float c0 = acc[mt][nt][half * 2];
                float c1 = acc[mt][nt][half * 2 + 1];
                p1 += c0 * __ldg(a1 + col) + c1 * __ldg(a1 + col + 1);
                p2 += c0 * __ldg(a2 + col) + c1 * __ldg(a2 + col + 1);
                if (n < NN)
                    *(float2*)&d_h[((size_t)n * NEV + e) * DD + col] = make_float2(c0, c1);
            }
            p1 += __shfl_xor_sync(0xffffffffu, p1, 1);
            p1 += __shfl_xor_sync(0xffffffffu, p1, 2);
            p2 += __shfl_xor_sync(0xffffffffu, p2, 1);
            p2 += __shfl_xor_sync(0xffffffffu, p2, 2);
            if (th == 0) {
                atomicAdd(&s1r[row_local], p1);   // exactly 2 adds/addr -> deterministic
                atomicAdd(&s2r[row_local], p2);
            }
        }
    }
    __syncthreads();
    if (t < 128) {
        int n = n0 + t;
        if (n < NN) {
            d_ssrc[n * NEV + e] = s1r[t];
            d_sdst[n * NEV + e] = s2r[t];
        }
    }
}

// ---------------- histogram of src degrees ----------------
__global__ void hist_kernel(const int* __restrict__ adj) {
    int i = blockIdx.x * blockDim.x + threadIdx.x;
    if (i < EE) atomicAdd(&d_cnt[adj[i]], 1);
}

// ---------------- single-block exclusive scan ----------------
__global__ void scan_kernel() {
    __shared__ int warp_sums[32];
    __shared__ int s_carry;
    int t = threadIdx.x, lane = t & 31, w = t >> 5;
    if (t == 0) s_carry = 0;
    __syncthreads();

    for (int base = 0; base < NN; base += 1024) {
        int i = base + t;
        int v = (i < NN) ? d_cnt[i] : 0;
        int s = v;
#pragma unroll
        for (int o = 1; o < 32; o <<= 1) {
            int y = __shfl_up_sync(0xffffffffu, s, o);
            if (lane >= o) s += y;
        }
        if (lane == 31) warp_sums[w] = s;
        __syncthreads();
        if (w == 0) {
            int ws = warp_sums[lane];
#pragma unroll
            for (int o = 1; o < 32; o <<= 1) {
                int y = __shfl_up_sync(0xffffffffu, ws, o);
                if (lane >= o) ws += y;
            }
            warp_sums[lane] = ws;
        }
        __syncthreads();
        int pre = s_carry + (w ? warp_sums[w - 1] : 0) + s - v;
        int tot = warp_sums[31];
        if (i < NN) { d_off[i] = pre; d_cur[i] = pre; }
        __syncthreads();
        if (t == 0) s_carry += tot;
        __syncthreads();
    }
    if (t == 0) d_off[NN] = s_carry;
}

// ---------------- scatter edges into CSR groups ----------------
__global__ void scatter_kernel(const int* __restrict__ adj) {
    int i = blockIdx.x * blockDim.x + threadIdx.x;
    if (i < EE) {
        int r = adj[i];
        int c = adj[EE + i];
        int p = atomicAdd(&d_cur[r], 1);
        d_csr[p] = c;
    }
}

// ---------------- global per-env max over all logits (incl. self loops) ----------------
__global__ void max_kernel(const int* __restrict__ adj) {
    const int tot = EE + NN;
    float lm[NEV];
#pragma unroll
    for (int e = 0; e < NEV; e++) lm[e] = -1e30f;

    int stride = gridDim.x * blockDim.x;
    for (int i = blockIdx.x * blockDim.x + threadIdx.x; i < tot; i += stride) {
        int s, d;
        if (i < EE) { s = adj[i]; d = adj[EE + i]; }
        else        { s = i - EE; d = s; }
#pragma unroll
        for (int e = 0; e < NEV; e++) {
            float v = lrelu(d_ssrc[s * NEV + e] + d_sdst[d * NEV + e]);
            lm[e] = fmaxf(lm[e], v);
        }
    }
#pragma unroll
    for (int o = 16; o > 0; o >>= 1)
#pragma unroll
        for (int e = 0; e < NEV; e++)
            lm[e] = fmaxf(lm[e], __shfl_xor_sync(0xffffffffu, lm[e], o));

    __shared__ float red[NEV][8];
    int lane = threadIdx.x & 31, wrp = threadIdx.x >> 5;
    if (lane == 0)
#pragma unroll
        for (int e = 0; e < NEV; e++) red[e][wrp] = lm[e];
    __syncthreads();
    if (wrp == 0) {
#pragma unroll
        for (int e = 0; e < NEV; e++) {
            float v = (lane < 8) ? red[e][lane] : -1e30f;
#pragma unroll
            for (int o = 4; o > 0; o >>= 1)
                v = fmaxf(v, __shfl_xor_sync(0xffffffffu, v, o));
            if (lane == 0) atomicMax(&d_maxu[e], fenc(v));
        }
    }
}

// ---------------- aggregate: one warp per node, fused final combine ----------------
__global__ void agg_kernel(const float* __restrict__ x,
                           const float* __restrict__ envw,
                           float* __restrict__ out) {
    int wid  = (blockIdx.x * blockDim.x + threadIdx.x) >> 5;
    int lane = threadIdx.x & 31;
    if (wid >= NN) return;
    int n = wid;

    float m[NEV], ss[NEV];
#pragma unroll
    for (int e = 0; e < NEV; e++) {
        m[e]  = fdec(d_maxu[e]);
        ss[e] = d_ssrc[n * NEV + e];
    }
    float4 sdn = *(const float4*)&d_sdst[n * NEV];
    float sdv[NEV] = {sdn.x, sdn.y, sdn.z, sdn.w};

    float acc[NEV][4];
    float den[NEV];

#pragma unroll
    for (int e = 0; e < NEV; e++) {
        float wv = __expf(lrelu(ss[e] + sdv[e]) - m[e]);
        den[e] = wv;
        float4 h4 = *(const float4*)&d_h[((size_t)n * NEV + e) * DD + lane * 4];
        acc[e][0] = wv * h4.x; acc[e][1] = wv * h4.y;
        acc[e][2] = wv * h4.z; acc[e][3] = wv * h4.w;
    }

    int start = d_off[n], end = d_off[n + 1];
    int e_l = lane & 3, j_l = lane >> 2;
    float ss_l = ss[e_l], m_l = m[e_l];

    for (int base = start; base < end; base += 8) {
        int idx = base + j_l;
        int dl = 0;
        float wl = 0.f;
        if (idx < end) {
            dl = d_csr[idx];
            float sv = d_sdst[dl * NEV + e_l];
            wl = __expf(lrelu(ss_l + sv) - m_l);
        }
        int cnt = end - base; if (cnt > 8) cnt = 8;
#pragma unroll
        for (int j = 0; j < 8; j++) {
            if (j >= cnt) break;
            int d = __shfl_sync(0xffffffffu, dl, j * 4);
            const float* hp = d_h + (size_t)d * NEV * DD + lane * 4;
#pragma unroll
            for (int e = 0; e < NEV; e++) {
                float wv = __shfl_sync(0xffffffffu, wl, j * 4 + e);
                float4 h4 = *(const float4*)(hp + e * DD);
                den[e] += wv;
                acc[e][0] += wv * h4.x; acc[e][1] += wv * h4.y;
                acc[e][2] += wv * h4.z; acc[e][3] += wv * h4.w;
            }
        }
    }

    float4 ew = *(const float4*)&envw[n * NEV];
    float ewv[NEV] = {ew.x, ew.y, ew.z, ew.w};
    float4 xv = *(const float4*)&x[(size_t)n * DD + lane * 4];
    float o0 = xv.x, o1 = xv.y, o2 = xv.z, o3 = xv.w;
#pragma unroll
    for (int e = 0; e < NEV; e++) {
        float c = ewv[e] / (den[e] + EPSV);
        o0 += c * acc[e][0]; o1 += c * acc[e][1];
        o2 += c * acc[e][2]; o3 += c * acc[e][3];
    }
    *(float4*)&out[(size_t)n * DD + lane * 4] = make_float4(o0, o1, o2, o3);
}

// ---------------- launcher ----------------
extern "C" void kernel_launch(void* const* d_in, const int* in_sizes, int n_in,
                              void* d_out, int out_size) {
    const float* x    = (const float*)d_in[0];
    const int*   adj  = (const int*)d_in[1];
    const float* envw = (const float*)d_in[2];
    const float* W    = (const float*)d_in[3];
    const float* a    = (const float*)d_in[4];
    float* out = (float*)d_out;

    cudaFuncSetAttribute(gemm_kernel, cudaFuncAttributeMaxDynamicSharedMemorySize, SMEM_BYTES);

    init_kernel<<<(NN + 255) / 256, 256>>>();
    wprep_kernel<<<(NEV * DD * DD + 255) / 256, 256>>>(W);
    hist_kernel<<<(EE + 255) / 256, 256>>>(adj);
    gemm_kernel<<<dim3((NN + 127) / 128, NEV), 256, SMEM_BYTES>>>(x, a);
    scan_kernel<<<1, 1024>>>();
    scatter_kernel<<<(EE + 255) / 256, 256>>>(adj);
    max_kernel<<<1024, 256>>>(adj);
    agg_kernel<<<(NN + 7) / 8, 256>>>(x, envw, out);
}

// round 4
// speedup vs baseline: 1.4255x; 1.2511x over previous
#include <cuda_runtime.h>
#include <cuda_bf16.h>
#include <cuda_fp16.h>
#include <cstdint>

#define NN 50000
#define EE 800000
#define DD 128
#define NEV 4
#define EPSV 1e-8f

// ---------------- scratch (device globals; no allocation allowed) ----------------
__device__ __half d_hh[(size_t)NN * NEV * DD];   // [n][e][f] fp16, 51.2 MB
__device__ float d_ssrc[NN * NEV];
__device__ float d_sdst[NN * NEV];
__device__ unsigned d_maxu[NEV];
__device__ int d_cnt[NN];
__device__ int d_off[NN + 1];
__device__ int d_cur[NN];
__device__ int d_csr[EE];
__device__ __nv_bfloat16 d_Wth[NEV * DD * DD];   // W^T hi: [e][f][k]
__device__ __nv_bfloat16 d_Wtl[NEV * DD * DD];   // W^T lo

__device__ __forceinline__ unsigned fenc(float f) {
    unsigned u = __float_as_uint(f);
    return (u & 0x80000000u) ? ~u : (u | 0x80000000u);
}
__device__ __forceinline__ float fdec(unsigned u) {
    u = (u & 0x80000000u) ? (u & 0x7fffffffu) : ~u;
    return __uint_as_float(u);
}
__device__ __forceinline__ float lrelu(float v) { return v > 0.f ? v : 0.01f * v; }

__device__ __forceinline__ uint32_t pack_bf2(float lo, float hi) {
    __nv_bfloat162 p;
    p.x = __float2bfloat16(lo);
    p.y = __float2bfloat16(hi);
    return *(uint32_t*)&p;
}

__device__ __forceinline__ void mma_bf16(float& c0, float& c1, float& c2, float& c3,
                                         uint32_t a0, uint32_t a1, uint32_t a2, uint32_t a3,
                                         uint32_t b0, uint32_t b1) {
    asm volatile(
        "mma.sync.aligned.m16n8k16.row.col.f32.bf16.bf16.f32 "
        "{%0,%1,%2,%3}, {%4,%5,%6,%7}, {%8,%9}, {%0,%1,%2,%3};\n"
        : "+f"(c0), "+f"(c1), "+f"(c2), "+f"(c3)
        : "r"(a0), "r"(a1), "r"(a2), "r"(a3), "r"(b0), "r"(b1));
}

// smem layout (word offsets), K staged in halves of 64.
// Row stride 36 words: bank(row,kw) = (4*row + kw) % 32 -> conflict-free frags.
#define ROWW 36
#define AH_W 0
#define AL_W (128 * ROWW)
#define BH_W (2 * 128 * ROWW)
#define BL_W (3 * 128 * ROWW)
#define SRED_W (4 * 128 * ROWW)
#define SMEM_WORDS (SRED_W + 256)
#define SMEM_BYTES (SMEM_WORDS * 4)

// ---------------- init ----------------
__global__ void init_kernel() {
    int i = blockIdx.x * blockDim.x + threadIdx.x;
    if (i < NN) d_cnt[i] = 0;
    if (i < NEV) d_maxu[i] = 0u;
}

// ---------------- prep: W^T split into bf16 hi/lo ----------------
__global__ void wprep_kernel(const float* __restrict__ W) {
    int i = blockIdx.x * blockDim.x + threadIdx.x;
    if (i >= NEV * DD * DD) return;
    int e = i >> 14;
    int k = (i >> 7) & 127;
    int f = i & 127;
    float v = W[i];
    __nv_bfloat16 hb = __float2bfloat16(v);
    __nv_bfloat16 lb = __float2bfloat16(v - __bfloat162float(hb));
    int o = ((e * DD + f) << 7) + k;
    d_Wth[o] = hb;
    d_Wtl[o] = lb;
}

// ---------------- GEMM: h = x @ W_e via mma.sync bf16x3 (K in 2 stages), fused s ----------------
__global__ void __launch_bounds__(256, 2) gemm_kernel(const float* __restrict__ x,
                                                      const float* __restrict__ a) {
    extern __shared__ uint32_t sm[];
    int t = threadIdx.x, lane = t & 31, wid = t >> 5;
    int e = blockIdx.y;
    int n0 = blockIdx.x * 128;

    float* s1r = (float*)(sm + SRED_W);
    float* s2r = s1r + 128;
    if (t < 128) { s1r[t] = 0.f; s2r[t] = 0.f; }

    int warpM = (wid >> 1) * 32;
    int warpN = (wid & 1) * 64;
    int g = lane >> 2, th = lane & 3;

    float acc[2][8][4];
#pragma unroll
    for (int mt = 0; mt < 2; mt++)
#pragma unroll
        for (int nt = 0; nt < 8; nt++)
#pragma unroll
            for (int j = 0; j < 4; j++) acc[mt][nt][j] = 0.f;

    const float4* x4 = (const float4*)x;
    const uint2* wh2 = (const uint2*)(d_Wth + e * DD * DD);
    const uint2* wl2 = (const uint2*)(d_Wtl + e * DD * DD);

#pragma unroll
    for (int s = 0; s < 2; s++) {
        if (s) __syncthreads();     // previous stage fully consumed

        // ---- fill A half-tile (cols s*64..s*64+63), split hi/lo ----
#pragma unroll
        for (int i = 0; i < 8; i++) {
            int q = i * 256 + t;
            int row = q >> 4;
            int c4 = q & 15;          // local float4 index (4 cols)
            float4 v = make_float4(0.f, 0.f, 0.f, 0.f);
            int n = n0 + row;
            if (n < NN) v = x4[(size_t)n * 32 + s * 16 + c4];
            float h0 = __bfloat162float(__float2bfloat16(v.x));
            float h1 = __bfloat162float(__float2bfloat16(v.y));
            float h2 = __bfloat162float(__float2bfloat16(v.z));
            float h3 = __bfloat162float(__float2bfloat16(v.w));
            uint2 hv, lv;
            hv.x = pack_bf2(v.x, v.y); hv.y = pack_bf2(v.z, v.w);
            lv.x = pack_bf2(v.x - h0, v.y - h1); lv.y = pack_bf2(v.z - h2, v.w - h3);
            *(uint2*)(sm + AH_W + row * ROWW + 2 * c4) = hv;
            *(uint2*)(sm + AL_W + row * ROWW + 2 * c4) = lv;
        }
        // ---- fill B half-tile (pre-transposed W^T, coalesced copy) ----
#pragma unroll
        for (int i = 0; i < 8; i++) {
            int q = i * 256 + t;
            int row = q >> 4;
            int kq = q & 15;
            *(uint2*)(sm + BH_W + row * ROWW + 2 * kq) = wh2[row * 32 + s * 16 + kq];
            *(uint2*)(sm + BL_W + row * ROWW + 2 * kq) = wl2[row * 32 + s * 16 + kq];
        }
        __syncthreads();

        // ---- mma over this K-half (4 k16 steps) ----
#pragma unroll
        for (int kk = 0; kk < 4; kk++) {
            int kb = kk * 8 + th;
            uint32_t ah[2][4], al[2][4];
#pragma unroll
            for (int mt = 0; mt < 2; mt++) {
                int r0 = warpM + mt * 16 + g;
                ah[mt][0] = sm[AH_W + r0 * ROWW + kb];
                ah[mt][1] = sm[AH_W + (r0 + 8) * ROWW + kb];
                ah[mt][2] = sm[AH_W + r0 * ROWW + kb + 4];
                ah[mt][3] = sm[AH_W + (r0 + 8) * ROWW + kb + 4];
                al[mt][0] = sm[AL_W + r0 * ROWW + kb];
                al[mt][1] = sm[AL_W + (r0 + 8) * ROWW + kb];
                al[mt][2] = sm[AL_W + r0 * ROWW + kb + 4];
                al[mt][3] = sm[AL_W + (r0 + 8) * ROWW + kb + 4];
            }
#pragma unroll
            for (int nt = 0; nt < 8; nt++) {
                int nIdx = warpN + nt * 8 + g;
                uint32_t bh0 = sm[BH_W + nIdx * ROWW + kb];
                uint32_t bh1 = sm[BH_W + nIdx * ROWW + kb + 4];
                uint32_t bl0 = sm[BL_W + nIdx * ROWW + kb];
                uint32_t bl1 = sm[BL_W + nIdx * ROWW + kb + 4];
#pragma unroll
                for (int mt = 0; mt < 2; mt++) {
                    mma_bf16(acc[mt][nt][0], acc[mt][nt][1], acc[mt][nt][2], acc[mt][nt][3],
                             ah[mt][0], ah[mt][1], ah[mt][2], ah[mt][3], bh0, bh1);
                    mma_bf16(acc[mt][nt][0], acc[mt][nt][1], acc[mt][nt][2], acc[mt][nt][3],
                             ah[mt][0], ah[mt][1], ah[mt][2], ah[mt][3], bl0, bl1);
                    mma_bf16(acc[mt][nt][0], acc[mt][nt][1], acc[mt][nt][2], acc[mt][nt][3],
                             al[mt][0], al[mt][1], al[mt][2], al[mt][3], bh0, bh1);
                }
            }
        }
    }

    // ---- epilogue: write h (fp16) + fused s projections (fp32) ----
    const float* a1 = a + e * 2 * DD;
    const float* a2 = a1 + DD;
#pragma unroll
    for (int mt = 0; mt < 2; mt++) {
#pragma unroll
        for (int half = 0; half < 2; half++) {
            int row_local = warpM + mt * 16 + half * 8 + g;
            int n = n0 + row_local;
            float p1 = 0.f, p2 = 0.f;
#pragma unroll
            for (int nt = 0; nt < 8; nt++) {
                int col = warpN + nt * 8 + 2 * th;
                float c0 = acc[mt][nt][half * 2];
                float c1 = acc[mt][nt][half * 2 + 1];
                p1 += c0 * __ldg(a1 + col) + c1 * __ldg(a1 + col + 1);
                p2 += c0 * __ldg(a2 + col) + c1 * __ldg(a2 + col + 1);
                if (n < NN)
                    *(__half2*)&d_hh[((size_t)n * NEV + e) * DD + col] = __floats2half2_rn(c0, c1);
            }
            p1 += __shfl_xor_sync(0xffffffffu, p1, 1);
            p1 += __shfl_xor_sync(0xffffffffu, p1, 2);
            p2 += __shfl_xor_sync(0xffffffffu, p2, 1);
            p2 += __shfl_xor_sync(0xffffffffu, p2, 2);
            if (th == 0) {
                atomicAdd(&s1r[row_local], p1);   // exactly 2 adds/addr -> deterministic
                atomicAdd(&s2r[row_local], p2);
            }
        }
    }
    __syncthreads();
    if (t < 128) {
        int n = n0 + t;
        if (n < NN) {
            d_ssrc[n * NEV + e] = s1r[t];
            d_sdst[n * NEV + e] = s2r[t];
        }
    }
}

// ---------------- histogram of src degrees ----------------
__global__ void hist_kernel(const int* __restrict__ adj) {
    int i = blockIdx.x * blockDim.x + threadIdx.x;
    if (i < EE) atomicAdd(&d_cnt[adj[i]], 1);
}

// ---------------- single-block exclusive scan ----------------
__global__ void scan_kernel() {
    __shared__ int warp_sums[32];
    __shared__ int s_carry;
    int t = threadIdx.x, lane = t & 31, w = t >> 5;
    if (t == 0) s_carry = 0;
    __syncthreads();

    for (int base = 0; base < NN; base += 1024) {
        int i = base + t;
        int v = (i < NN) ? d_cnt[i] : 0;
        int s = v;
#pragma unroll
        for (int o = 1; o < 32; o <<= 1) {
            int y = __shfl_up_sync(0xffffffffu, s, o);
            if (lane >= o) s += y;
        }
        if (lane == 31) warp_sums[w] = s;
        __syncthreads();
        if (w == 0) {
            int ws = warp_sums[lane];
#pragma unroll
            for (int o = 1; o < 32; o <<= 1) {
                int y = __shfl_up_sync(0xffffffffu, ws, o);
                if (lane >= o) ws += y;
            }
            warp_sums[lane] = ws;
        }
        __syncthreads();
        int pre = s_carry + (w ? warp_sums[w - 1] : 0) + s - v;
        int tot = warp_sums[31];
        if (i < NN) { d_off[i] = pre; d_cur[i] = pre; }
        __syncthreads();
        if (t == 0) s_carry += tot;
        __syncthreads();
    }
    if (t == 0) d_off[NN] = s_carry;
}

// ---------------- scatter edges into CSR groups ----------------
__global__ void scatter_kernel(const int* __restrict__ adj) {
    int i = blockIdx.x * blockDim.x + threadIdx.x;
    if (i < EE) {
        int r = adj[i];
        int c = adj[EE + i];
        int p = atomicAdd(&d_cur[r], 1);
        d_csr[p] = c;
    }
}

// ---------------- global per-env max over all logits (incl. self loops) ----------------
__global__ void max_kernel(const int* __restrict__ adj) {
    const int tot = EE + NN;
    float lm[NEV];
#pragma unroll
    for (int e = 0; e < NEV; e++) lm[e] = -1e30f;

    int stride = gridDim.x * blockDim.x;
    for (int i = blockIdx.x * blockDim.x + threadIdx.x; i < tot; i += stride) {
        int s, d;
        if (i < EE) { s = adj[i]; d = adj[EE + i]; }
        else        { s = i - EE; d = s; }
#pragma unroll
        for (int e = 0; e < NEV; e++) {
            float v = lrelu(d_ssrc[s * NEV + e] + d_sdst[d * NEV + e]);
            lm[e] = fmaxf(lm[e], v);
        }
    }
#pragma unroll
    for (int o = 16; o > 0; o >>= 1)
#pragma unroll
        for (int e = 0; e < NEV; e++)
            lm[e] = fmaxf(lm[e], __shfl_xor_sync(0xffffffffu, lm[e], o));

    __shared__ float red[NEV][8];
    int lane = threadIdx.x & 31, wrp = threadIdx.x >> 5;
    if (lane == 0)
#pragma unroll
        for (int e = 0; e < NEV; e++) red[e][wrp] = lm[e];
    __syncthreads();
    if (wrp == 0) {
#pragma unroll
        for (int e = 0; e < NEV; e++) {
            float v = (lane < 8) ? red[e][lane] : -1e30f;
#pragma unroll
            for (int o = 4; o > 0; o >>= 1)
                v = fmaxf(v, __shfl_xor_sync(0xffffffffu, v, o));
            if (lane == 0) atomicMax(&d_maxu[e], fenc(v));
        }
    }
}

// ---------------- aggregate: one warp per node, fp16 h reads, fused final combine ----------------
__global__ void agg_kernel(const float* __restrict__ x,
                           const float* __restrict__ envw,
                           float* __restrict__ out) {
    int wid  = (blockIdx.x * blockDim.x + threadIdx.x) >> 5;
    int lane = threadIdx.x & 31;
    if (wid >= NN) return;
    int n = wid;

    float m[NEV], ss[NEV];
#pragma unroll
    for (int e = 0; e < NEV; e++) {
        m[e]  = fdec(d_maxu[e]);
        ss[e] = d_ssrc[n * NEV + e];
    }
    float4 sdn = *(const float4*)&d_sdst[n * NEV];
    float sdv[NEV] = {sdn.x, sdn.y, sdn.z, sdn.w};

    float acc[NEV][4];
    float den[NEV];

    // self loop
#pragma unroll
    for (int e = 0; e < NEV; e++) {
        float wv = __expf(lrelu(ss[e] + sdv[e]) - m[e]);
        den[e] = wv;
        uint2 u = *(const uint2*)&d_hh[((size_t)n * NEV + e) * DD + lane * 4];
        float2 f0 = __half22float2(*(__half2*)&u.x);
        float2 f1 = __half22float2(*(__half2*)&u.y);
        acc[e][0] = wv * f0.x; acc[e][1] = wv * f0.y;
        acc[e][2] = wv * f1.x; acc[e][3] = wv * f1.y;
    }

    int start = d_off[n], end = d_off[n + 1];
    int e_l = lane & 3, j_l = lane >> 2;
    float ss_l = ss[e_l], m_l = m[e_l];

    for (int base = start; base < end; base += 8) {
        int idx = base + j_l;
        int dl = 0;
        float wl = 0.f;
        if (idx < end) {
            dl = d_csr[idx];
            float sv = d_sdst[dl * NEV + e_l];
            wl = __expf(lrelu(ss_l + sv) - m_l);
        }
        int cnt = end - base; if (cnt > 8) cnt = 8;
#pragma unroll
        for (int j = 0; j < 8; j++) {
            if (j >= cnt) break;
            int d = __shfl_sync(0xffffffffu, dl, j * 4);
            const __half* hp = d_hh + (size_t)d * NEV * DD + lane * 4;
#pragma unroll
            for (int e = 0; e < NEV; e++) {
                float wv = __shfl_sync(0xffffffffu, wl, j * 4 + e);
                uint2 u = *(const uint2*)(hp + e * DD);
                float2 f0 = __half22float2(*(__half2*)&u.x);
                float2 f1 = __half22float2(*(__half2*)&u.y);
                den[e] += wv;
                acc[e][0] += wv * f0.x; acc[e][1] += wv * f0.y;
                acc[e][2] += wv * f1.x; acc[e][3] += wv * f1.y;
            }
        }
    }

    float4 ew = *(const float4*)&envw[n * NEV];
    float ewv[NEV] = {ew.x, ew.y, ew.z, ew.w};
    float4 xv = *(const float4*)&x[(size_t)n * DD + lane * 4];
    float o0 = xv.x, o1 = xv.y, o2 = xv.z, o3 = xv.w;
#pragma unroll
    for (int e = 0; e < NEV; e++) {
        float c = ewv[e] / (den[e] + EPSV);
        o0 += c * acc[e][0]; o1 += c * acc[e][1];
        o2 += c * acc[e][2]; o3 += c * acc[e][3];
    }
    *(float4*)&out[(size_t)n * DD + lane * 4] = make_float4(o0, o1, o2, o3);
}

// ---------------- launcher ----------------
extern "C" void kernel_launch(void* const* d_in, const int* in_sizes, int n_in,
                              void* d_out, int out_size) {
    const float* x    = (const float*)d_in[0];
    const int*   adj  = (const int*)d_in[1];
    const float* envw = (const float*)d_in[2];
    const float* W    = (const float*)d_in[3];
    const float* a    = (const float*)d_in[4];
    float* out = (float*)d_out;

    cudaFuncSetAttribute(gemm_kernel, cudaFuncAttributeMaxDynamicSharedMemorySize, SMEM_BYTES);

    init_kernel<<<(NN + 255) / 256, 256>>>();
    wprep_kernel<<<(NEV * DD * DD + 255) / 256, 256>>>(W);
    hist_kernel<<<(EE + 255) / 256, 256>>>(adj);
    gemm_kernel<<<dim3((NN + 127) / 128, NEV), 256, SMEM_BYTES>>>(x, a);
    scan_kernel<<<1, 1024>>>();
    scatter_kernel<<<(EE + 255) / 256, 256>>>(adj);
    max_kernel<<<1024, 256>>>(adj);
    agg_kernel<<<(NN + 7) / 8, 256>>>(x, envw, out);
}

// round 6
// speedup vs baseline: 1.5884x; 1.1143x over previous
#include <cuda_runtime.h>
#include <cuda_bf16.h>
#include <cuda_fp16.h>
#include <cstdint>

#define NN 50000
#define EE 800000
#define DD 128
#define NEV 4
#define EPSV 1e-8f

// ---------------- scratch (device globals; no allocation allowed) ----------------
__device__ __half d_hh[(size_t)NN * NEV * DD];   // [n][e][f] fp16, 51.2 MB
__device__ float d_ssrc[NN * NEV];
__device__ float d_sdst[NN * NEV];
__device__ unsigned d_maxu[NEV];
__device__ int d_cnt[NN];
__device__ int d_off[NN + 1];
__device__ int d_cur[NN];
__device__ int d_csr[EE];
__device__ __nv_bfloat16 d_Wth[NEV * DD * DD];   // W^T hi: [e][f][k]
__device__ __nv_bfloat16 d_Wtl[NEV * DD * DD];   // W^T lo

__device__ __forceinline__ unsigned fenc(float f) {
    unsigned u = __float_as_uint(f);
    return (u & 0x80000000u) ? ~u : (u | 0x80000000u);
}
__device__ __forceinline__ float fdec(unsigned u) {
    u = (u & 0x80000000u) ? (u & 0x7fffffffu) : ~u;
    return __uint_as_float(u);
}
__device__ __forceinline__ float lrelu(float v) { return v > 0.f ? v : 0.01f * v; }

__device__ __forceinline__ uint32_t pack_bf2(float lo, float hi) {
    __nv_bfloat162 p;
    p.x = __float2bfloat16(lo);
    p.y = __float2bfloat16(hi);
    return *(uint32_t*)&p;
}

__device__ __forceinline__ void mma_bf16(float& c0, float& c1, float& c2, float& c3,
                                         uint32_t a0, uint32_t a1, uint32_t a2, uint32_t a3,
                                         uint32_t b0, uint32_t b1) {
    asm volatile(
        "mma.sync.aligned.m16n8k16.row.col.f32.bf16.bf16.f32 "
        "{%0,%1,%2,%3}, {%4,%5,%6,%7}, {%8,%9}, {%0,%1,%2,%3};\n"
        : "+f"(c0), "+f"(c1), "+f"(c2), "+f"(c3)
        : "r"(a0), "r"(a1), "r"(a2), "r"(a3), "r"(b0), "r"(b1));
}

__device__ __forceinline__ void ldsm_x4(uint32_t* r, uint32_t addr) {
    asm volatile("ldmatrix.sync.aligned.m8n8.x4.shared.b16 {%0,%1,%2,%3}, [%4];"
                 : "=r"(r[0]), "=r"(r[1]), "=r"(r[2]), "=r"(r[3]) : "r"(addr));
}

// smem layout (word offsets), K staged in halves of 64.
// Row stride 36 words: rows are 4 banks apart -> ldmatrix conflict-free, 16B aligned (144B).
#define ROWW 36
#define AH_W 0
#define AL_W (128 * ROWW)
#define BH_W (2 * 128 * ROWW)
#define BL_W (3 * 128 * ROWW)
#define SRED_W (4 * 128 * ROWW)
#define SMEM_WORDS (SRED_W + 256)
#define SMEM_BYTES (SMEM_WORDS * 4)
#define MT_STRIDE_B (16 * ROWW * 4)          // 16 rows, bytes
#define LO_OFF_B (128 * ROWW * 4)            // hi->lo array distance, bytes

// ---------------- init + W prep (merged) ----------------
__global__ void prep_kernel(const float* __restrict__ W) {
    int i = blockIdx.x * blockDim.x + threadIdx.x;
    if (i < NN) d_cnt[i] = 0;
    if (i < NEV) d_maxu[i] = 0u;
    if (i < NEV * DD * DD) {
        int e = i >> 14;
        int k = (i >> 7) & 127;
        int f = i & 127;
        float v = W[i];
        __nv_bfloat16 hb = __float2bfloat16(v);
        __nv_bfloat16 lb = __float2bfloat16(v - __bfloat162float(hb));
        int o = ((e * DD + f) << 7) + k;
        d_Wth[o] = hb;
        d_Wtl[o] = lb;
    }
}

// ---------------- GEMM: h = x @ W_e via mma.sync bf16x3 + ldmatrix, fused s ----------------
__global__ void __launch_bounds__(256, 2) gemm_kernel(const float* __restrict__ x,
                                                      const float* __restrict__ a) {
    extern __shared__ uint32_t sm[];
    uint32_t smb = (uint32_t)__cvta_generic_to_shared(sm);
    int t = threadIdx.x, lane = t & 31, wid = t >> 5;
    int e = blockIdx.y;
    int n0 = blockIdx.x * 128;

    float* s1r = (float*)(sm + SRED_W);
    float* s2r = s1r + 128;
    if (t < 128) { s1r[t] = 0.f; s2r[t] = 0.f; }

    int warpM = (wid >> 1) * 32;
    int warpN = (wid & 1) * 64;
    int g = lane >> 2, th = lane & 3;
    int lrow = lane & 15, lhalf = lane >> 4;

    // ldmatrix base addresses (bytes, shared space)
    uint32_t aab = smb + (uint32_t)(AH_W + (warpM + lrow) * ROWW + lhalf * 4) * 4;
    uint32_t bab = smb + (uint32_t)(BH_W + (warpN + lrow) * ROWW + lhalf * 4) * 4;

    float acc[2][8][4];
#pragma unroll
    for (int mt = 0; mt < 2; mt++)
#pragma unroll
        for (int nt = 0; nt < 8; nt++)
#pragma unroll
            for (int j = 0; j < 4; j++) acc[mt][nt][j] = 0.f;

    const float4* x4 = (const float4*)x;
    const uint2* wh2 = (const uint2*)(d_Wth + e * DD * DD);
    const uint2* wl2 = (const uint2*)(d_Wtl + e * DD * DD);

#pragma unroll
    for (int s = 0; s < 2; s++) {
        if (s) __syncthreads();

        // ---- fill A half-tile (cols s*64..+63), split hi/lo ----
#pragma unroll
        for (int i = 0; i < 8; i++) {
            int q = i * 256 + t;
            int row = q >> 4;
            int c4 = q & 15;
            float4 v = make_float4(0.f, 0.f, 0.f, 0.f);
            int n = n0 + row;
            if (n < NN) v = x4[(size_t)n * 32 + s * 16 + c4];
            float h0 = __bfloat162float(__float2bfloat16(v.x));
            float h1 = __bfloat162float(__float2bfloat16(v.y));
            float h2 = __bfloat162float(__float2bfloat16(v.z));
            float h3 = __bfloat162float(__float2bfloat16(v.w));
            uint2 hv, lv;
            hv.x = pack_bf2(v.x, v.y); hv.y = pack_bf2(v.z, v.w);
            lv.x = pack_bf2(v.x - h0, v.y - h1); lv.y = pack_bf2(v.z - h2, v.w - h3);
            *(uint2*)(sm + AH_W + row * ROWW + 2 * c4) = hv;
            *(uint2*)(sm + AL_W + row * ROWW + 2 * c4) = lv;
        }
        // ---- fill B half-tile (pre-transposed W^T, coalesced copy) ----
#pragma unroll
        for (int i = 0; i < 8; i++) {
            int q = i * 256 + t;
            int row = q >> 4;
            int kq = q & 15;
            *(uint2*)(sm + BH_W + row * ROWW + 2 * kq) = wh2[row * 32 + s * 16 + kq];
            *(uint2*)(sm + BL_W + row * ROWW + 2 * kq) = wl2[row * 32 + s * 16 + kq];
        }
        __syncthreads();

        // ---- mma over this K-half (4 k16 steps) ----
#pragma unroll
        for (int kk = 0; kk < 4; kk++) {
            uint32_t kb = kk * 32;
            uint32_t ah[2][4], al[2][4], bh[4][4], bl[4][4];
            ldsm_x4(ah[0], aab + kb);
            ldsm_x4(ah[1], aab + MT_STRIDE_B + kb);
            ldsm_x4(al[0], aab + LO_OFF_B + kb);
            ldsm_x4(al[1], aab + LO_OFF_B + MT_STRIDE_B + kb);
#pragma unroll
            for (int q = 0; q < 4; q++) {
                ldsm_x4(bh[q], bab + q * MT_STRIDE_B + kb);
                ldsm_x4(bl[q], bab + LO_OFF_B + q * MT_STRIDE_B + kb);
            }
#pragma unroll
            for (int nt = 0; nt < 8; nt++) {
                int p = nt >> 1, sl = nt & 1;
                uint32_t b0h = bh[p][sl], b1h = bh[p][2 + sl];
                uint32_t b0l = bl[p][sl], b1l = bl[p][2 + sl];
#pragma unroll
                for (int mt = 0; mt < 2; mt++) {
                    mma_bf16(acc[mt][nt][0], acc[mt][nt][1], acc[mt][nt][2], acc[mt][nt][3],
                             ah[mt][0], ah[mt][1], ah[mt][2], ah[mt][3], b0h, b1h);
                    mma_bf16(acc[mt][nt][0], acc[mt][nt][1], acc[mt][nt][2], acc[mt][nt][3],
                             ah[mt][0], ah[mt][1], ah[mt][2], ah[mt][3], b0l, b1l);
                    mma_bf16(acc[mt][nt][0], acc[mt][nt][1], acc[mt][nt][2], acc[mt][nt][3],
                             al[mt][0], al[mt][1], al[mt][2], al[mt][3], b0h, b1h);
                }
            }
        }
    }

    // ---- epilogue: write h (fp16) + fused s projections (fp32) ----
    const float* a1 = a + e * 2 * DD;
    const float* a2 = a1 + DD;
#pragma unroll
    for (int mt = 0; mt < 2; mt++) {
#pragma unroll
        for (int half = 0; half < 2; half++) {
            int row_local = warpM + mt * 16 + half * 8 + g;
            int n = n0 + row_local;
            float p1 = 0.f, p2 = 0.f;
#pragma unroll
            for (int nt = 0; nt < 8; nt++) {
                int col = warpN + nt * 8 + 2 * th;
                float c0 = acc[mt][nt][half * 2];
                float c1 = acc[mt][nt][half * 2 + 1];
                p1 += c0 * __ldg(a1 + col) + c1 * __ldg(a1 + col + 1);
                p2 += c0 * __ldg(a2 + col) + c1 * __ldg(a2 + col + 1);
                if (n < NN)
                    *(__half2*)&d_hh[((size_t)n * NEV + e) * DD + col] = __floats2half2_rn(c0, c1);
            }
            p1 += __shfl_xor_sync(0xffffffffu, p1, 1);
            p1 += __shfl_xor_sync(0xffffffffu, p1, 2);
            p2 += __shfl_xor_sync(0xffffffffu, p2, 1);
            p2 += __shfl_xor_sync(0xffffffffu, p2, 2);
            if (th == 0) {
                atomicAdd(&s1r[row_local], p1);   // exactly 2 adds/addr -> deterministic
                atomicAdd(&s2r[row_local], p2);
            }
        }
    }
    __syncthreads();
    if (t < 128) {
        int n = n0 + t;
        if (n < NN) {
            d_ssrc[n * NEV + e] = s1r[t];
            d_sdst[n * NEV + e] = s2r[t];
        }
    }
}

// ---------------- histogram of src degrees ----------------
__global__ void hist_kernel(const int* __restrict__ adj) {
    int i = blockIdx.x * blockDim.x + threadIdx.x;
    if (i < EE) atomicAdd(&d_cnt[adj[i]], 1);
}

// ---------------- single-block exclusive scan ----------------
__global__ void scan_kernel() {
    __shared__ int warp_sums[32];
    __shared__ int s_carry;
    int t = threadIdx.x, lane = t & 31, w = t >> 5;
    if (t == 0) s_carry = 0;
    __syncthreads();

    for (int base = 0; base < NN; base += 1024) {
        int i = base + t;
        int v = (i < NN) ? d_cnt[i] : 0;
        int s = v;
#pragma unroll
        for (int o = 1; o < 32; o <<= 1) {
            int y = __shfl_up_sync(0xffffffffu, s, o);
            if (lane >= o) s += y;
        }
        if (lane == 31) warp_sums[w] = s;
        __syncthreads();
        if (w == 0) {
            int ws = warp_sums[lane];
#pragma unroll
            for (int o = 1; o < 32; o <<= 1) {
                int y = __shfl_up_sync(0xffffffffu, ws, o);
                if (lane >= o) ws += y;
            }
            warp_sums[lane] = ws;
        }
        __syncthreads();
        int pre = s_carry + (w ? warp_sums[w - 1] : 0) + s - v;
        int tot = warp_sums[31];
        if (i < NN) { d_off[i] = pre; d_cur[i] = pre; }
        __syncthreads();
        if (t == 0) s_carry += tot;
        __syncthreads();
    }
    if (t == 0) d_off[NN] = s_carry;
}

// ---------------- scatter edges into CSR groups ----------------
__global__ void scatter_kernel(const int* __restrict__ adj) {
    int i = blockIdx.x * blockDim.x + threadIdx.x;
    if (i < EE) {
        int r = adj[i];
        int c = adj[EE + i];
        int p = atomicAdd(&d_cur[r], 1);
        d_csr[p] = c;
    }
}

// ---------------- global per-env max over all logits (incl. self loops) ----------------
__global__ void max_kernel(const int* __restrict__ adj) {
    const int tot = EE + NN;
    float lm[NEV];
#pragma unroll
    for (int e = 0; e < NEV; e++) lm[e] = -1e30f;

    int stride = gridDim.x * blockDim.x;
    for (int i = blockIdx.x * blockDim.x + threadIdx.x; i < tot; i += stride) {
        int s, d;
        if (i < EE) { s = adj[i]; d = adj[EE + i]; }
        else        { s = i - EE; d = s; }
#pragma unroll
        for (int e = 0; e < NEV; e++) {
            float v = lrelu(d_ssrc[s * NEV + e] + d_sdst[d * NEV + e]);
            lm[e] = fmaxf(lm[e], v);
        }
    }
#pragma unroll
    for (int o = 16; o > 0; o >>= 1)
#pragma unroll
        for (int e = 0; e < NEV; e++)
            lm[e] = fmaxf(lm[e], __shfl_xor_sync(0xffffffffu, lm[e], o));

    __shared__ float red[NEV][8];
    int lane = threadIdx.x & 31, wrp = threadIdx.x >> 5;
    if (lane == 0)
#pragma unroll
        for (int e = 0; e < NEV; e++) red[e][wrp] = lm[e];
    __syncthreads();
    if (wrp == 0) {
#pragma unroll
        for (int e = 0; e < NEV; e++) {
            float v = (lane < 8) ? red[e][lane] : -1e30f;
#pragma unroll
            for (int o = 4; o > 0; o >>= 1)
                v = fmaxf(v, __shfl_xor_sync(0xffffffffu, v, o));
            if (lane == 0) atomicMax(&d_maxu[e], fenc(v));
        }
    }
}

// ---------------- aggregate: one warp per node, fp16 h reads, fused final combine ----------------
__global__ void agg_kernel(const float* __restrict__ x,
                           const float* __restrict__ envw,
                           float* __restrict__ out) {
    int wid  = (blockIdx.x * blockDim.x + threadIdx.x) >> 5;
    int lane = threadIdx.x & 31;
    if (wid >= NN) return;
    int n = wid;

    float m[NEV], ss[NEV];
#pragma unroll
    for (int e = 0; e < NEV; e++) {
        m[e]  = fdec(d_maxu[e]);
        ss[e] = d_ssrc[n * NEV + e];
    }
    float4 sdn = *(const float4*)&d_sdst[n * NEV];
    float sdv[NEV] = {sdn.x, sdn.y, sdn.z, sdn.w};

    float acc[NEV][4];
    float den[NEV];

    // self loop
#pragma unroll
    for (int e = 0; e < NEV; e++) {
        float wv = __expf(lrelu(ss[e] + sdv[e]) - m[e]);
        den[e] = wv;
        uint2 u = *(const uint2*)&d_hh[((size_t)n * NEV + e) * DD + lane * 4];
        float2 f0 = __half22float2(*(__half2*)&u.x);
        float2 f1 = __half22float2(*(__half2*)&u.y);
        acc[e][0] = wv * f0.x; acc[e][1] = wv * f0.y;
        acc[e][2] = wv * f1.x; acc[e][3] = wv * f1.y;
    }

    int start = d_off[n], end = d_off[n + 1];
    int e_l = lane & 3, j_l = lane >> 2;
    float ss_l = ss[e_l], m_l = m[e_l];

    for (int base = start; base < end; base += 8) {
        int idx = base + j_l;
        int dl = 0;
        float wl = 0.f;
        if (idx < end) {
            dl = d_csr[idx];
            float sv = d_sdst[dl * NEV + e_l];
            wl = __expf(lrelu(ss_l + sv) - m_l);
        }
        int cnt = end - base; if (cnt > 8) cnt = 8;
#pragma unroll
        for (int j = 0; j < 8; j++) {
            if (j >= cnt) break;
            int d = __shfl_sync(0xffffffffu, dl, j * 4);
            const __half* hp = d_hh + (size_t)d * NEV * DD + lane * 4;
#pragma unroll
            for (int e = 0; e < NEV; e++) {
                float wv = __shfl_sync(0xffffffffu, wl, j * 4 + e);
                uint2 u = *(const uint2*)(hp + e * DD);
                float2 f0 = __half22float2(*(__half2*)&u.x);
                float2 f1 = __half22float2(*(__half2*)&u.y);
                den[e] += wv;
                acc[e][0] += wv * f0.x; acc[e][1] += wv * f0.y;
                acc[e][2] += wv * f1.x; acc[e][3] += wv * f1.y;
            }
        }
    }

    float4 ew = *(const float4*)&envw[n * NEV];
    float ewv[NEV] = {ew.x, ew.y, ew.z, ew.w};
    float4 xv = *(const float4*)&x[(size_t)n * DD + lane * 4];
    float o0 = xv.x, o1 = xv.y, o2 = xv.z, o3 = xv.w;
#pragma unroll
    for (int e = 0; e < NEV; e++) {
        float c = ewv[e] / (den[e] + EPSV);
        o0 += c * acc[e][0]; o1 += c * acc[e][1];
        o2 += c * acc[e][2]; o3 += c * acc[e][3];
    }
    *(float4*)&out[(size_t)n * DD + lane * 4] = make_float4(o0, o1, o2, o3);
}

// ---------------- launcher ----------------
extern "C" void kernel_launch(void* const* d_in, const int* in_sizes, int n_in,
                              void* d_out, int out_size) {
    const float* x    = (const float*)d_in[0];
    const int*   adj  = (const int*)d_in[1];
    const float* envw = (const float*)d_in[2];
    const float* W    = (const float*)d_in[3];
    const float* a    = (const float*)d_in[4];
    float* out = (float*)d_out;

    cudaFuncSetAttribute(gemm_kernel, cudaFuncAttributeMaxDynamicSharedMemorySize, SMEM_BYTES);

    prep_kernel<<<(NEV * DD * DD + 255) / 256, 256>>>(W);
    hist_kernel<<<(EE + 255) / 256, 256>>>(adj);
    gemm_kernel<<<dim3((NN + 127) / 128, NEV), 256, SMEM_BYTES>>>(x, a);
    scan_kernel<<<1, 1024>>>();
    scatter_kernel<<<(EE + 255) / 256, 256>>>(adj);
    max_kernel<<<1024, 256>>>(adj);
    agg_kernel<<<(NN + 7) / 8, 256>>>(x, envw, out);
}

// round 8
// speedup vs baseline: 1.8671x; 1.1755x over previous
#include <cuda_runtime.h>
#include <cuda_bf16.h>
#include <cuda_fp16.h>
#include <cstdint>

#define NN 50000
#define EE 800000
#define DD 128
#define NEV 4
#define EPSV 1e-8f
#define NBLK ((NN + 255) / 256)   // 196

// ---------------- scratch (device globals; no allocation allowed) ----------------
__device__ __half d_hh[(size_t)NN * NEV * DD];   // [n][e][f] fp16, 51.2 MB
__device__ float d_ssrc[NN * NEV];
__device__ float d_sdst[NN * NEV];
__device__ unsigned d_maxu[NEV];
__device__ int d_cnt[NN];
__device__ int d_off[NN + 1];
__device__ int d_cur[NN];
__device__ int d_csr[EE];
__device__ int d_bsum[NBLK];
__device__ int d_boff[NBLK];
__device__ __nv_bfloat16 d_Wth[NEV * DD * DD];   // W^T hi: [e][f][k]
__device__ __nv_bfloat16 d_Wtl[NEV * DD * DD];   // W^T lo

__device__ __forceinline__ unsigned fenc(float f) {
    unsigned u = __float_as_uint(f);
    return (u & 0x80000000u) ? ~u : (u | 0x80000000u);
}
__device__ __forceinline__ float fdec(unsigned u) {
    u = (u & 0x80000000u) ? (u & 0x7fffffffu) : ~u;
    return __uint_as_float(u);
}
__device__ __forceinline__ float lrelu(float v) { return v > 0.f ? v : 0.01f * v; }

__device__ __forceinline__ uint32_t pack_bf2(float lo, float hi) {
    __nv_bfloat162 p;
    p.x = __float2bfloat16(lo);
    p.y = __float2bfloat16(hi);
    return *(uint32_t*)&p;
}

__device__ __forceinline__ void mma_bf16(float& c0, float& c1, float& c2, float& c3,
                                         uint32_t a0, uint32_t a1, uint32_t a2, uint32_t a3,
                                         uint32_t b0, uint32_t b1) {
    asm volatile(
        "mma.sync.aligned.m16n8k16.row.col.f32.bf16.bf16.f32 "
        "{%0,%1,%2,%3}, {%4,%5,%6,%7}, {%8,%9}, {%0,%1,%2,%3};\n"
        : "+f"(c0), "+f"(c1), "+f"(c2), "+f"(c3)
        : "r"(a0), "r"(a1), "r"(a2), "r"(a3), "r"(b0), "r"(b1));
}

__device__ __forceinline__ void ldsm_x4(uint32_t* r, uint32_t addr) {
    asm volatile("ldmatrix.sync.aligned.m8n8.x4.shared.b16 {%0,%1,%2,%3}, [%4];"
                 : "=r"(r[0]), "=r"(r[1]), "=r"(r[2]), "=r"(r[3]) : "r"(addr));
}

// smem layout (word offsets), K staged in halves of 64.
#define ROWW 36
#define AH_W 0
#define AL_W (128 * ROWW)
#define BH_W (2 * 128 * ROWW)
#define BL_W (3 * 128 * ROWW)
#define SRED_W (4 * 128 * ROWW)
#define SMEM_WORDS (SRED_W + 256)
#define SMEM_BYTES (SMEM_WORDS * 4)
#define MT_STRIDE_B (16 * ROWW * 4)
#define LO_OFF_B (128 * ROWW * 4)

// ---------------- init + W prep (merged) ----------------
__global__ void prep_kernel(const float* __restrict__ W) {
    int i = blockIdx.x * blockDim.x + threadIdx.x;
    if (i < NN) d_cnt[i] = 0;
    if (i < NEV) d_maxu[i] = 0u;
    if (i < NEV * DD * DD) {
        int e = i >> 14;
        int k = (i >> 7) & 127;
        int f = i & 127;
        float v = W[i];
        __nv_bfloat16 hb = __float2bfloat16(v);
        __nv_bfloat16 lb = __float2bfloat16(v - __bfloat162float(hb));
        int o = ((e * DD + f) << 7) + k;
        d_Wth[o] = hb;
        d_Wtl[o] = lb;
    }
}

// ---------------- GEMM: h = x @ W_e via mma.sync bf16x3 + ldmatrix, fused s ----------------
__global__ void __launch_bounds__(256, 2) gemm_kernel(const float* __restrict__ x,
                                                      const float* __restrict__ a) {
    extern __shared__ uint32_t sm[];
    uint32_t smb = (uint32_t)__cvta_generic_to_shared(sm);
    int t = threadIdx.x, lane = t & 31, wid = t >> 5;
    int e = blockIdx.y;
    int n0 = blockIdx.x * 128;

    float* s1r = (float*)(sm + SRED_W);
    float* s2r = s1r + 128;
    if (t < 128) { s1r[t] = 0.f; s2r[t] = 0.f; }

    int warpM = (wid >> 1) * 32;
    int warpN = (wid & 1) * 64;
    int g = lane >> 2, th = lane & 3;
    int lrow = lane & 15, lhalf = lane >> 4;

    uint32_t aab = smb + (uint32_t)(AH_W + (warpM + lrow) * ROWW + lhalf * 4) * 4;
    uint32_t bab = smb + (uint32_t)(BH_W + (warpN + lrow) * ROWW + lhalf * 4) * 4;

    float acc[2][8][4];
#pragma unroll
    for (int mt = 0; mt < 2; mt++)
#pragma unroll
        for (int nt = 0; nt < 8; nt++)
#pragma unroll
            for (int j = 0; j < 4; j++) acc[mt][nt][j] = 0.f;

    const float4* x4 = (const float4*)x;
    const uint2* wh2 = (const uint2*)(d_Wth + e * DD * DD);
    const uint2* wl2 = (const uint2*)(d_Wtl + e * DD * DD);

#pragma unroll
    for (int s = 0; s < 2; s++) {
        if (s) __syncthreads();

#pragma unroll
        for (int i = 0; i < 8; i++) {
            int q = i * 256 + t;
            int row = q >> 4;
            int c4 = q & 15;
            float4 v = make_float4(0.f, 0.f, 0.f, 0.f);
            int n = n0 + row;
            if (n < NN) v = x4[(size_t)n * 32 + s * 16 + c4];
            float h0 = __bfloat162float(__float2bfloat16(v.x));
            float h1 = __bfloat162float(__float2bfloat16(v.y));
            float h2 = __bfloat162float(__float2bfloat16(v.z));
            float h3 = __bfloat162float(__float2bfloat16(v.w));
            uint2 hv, lv;
            hv.x = pack_bf2(v.x, v.y); hv.y = pack_bf2(v.z, v.w);
            lv.x = pack_bf2(v.x - h0, v.y - h1); lv.y = pack_bf2(v.z - h2, v.w - h3);
            *(uint2*)(sm + AH_W + row * ROWW + 2 * c4) = hv;
            *(uint2*)(sm + AL_W + row * ROWW + 2 * c4) = lv;
        }
#pragma unroll
        for (int i = 0; i < 8; i++) {
            int q = i * 256 + t;
            int row = q >> 4;
            int kq = q & 15;
            *(uint2*)(sm + BH_W + row * ROWW + 2 * kq) = wh2[row * 32 + s * 16 + kq];
            *(uint2*)(sm + BL_W + row * ROWW + 2 * kq) = wl2[row * 32 + s * 16 + kq];
        }
        __syncthreads();

#pragma unroll
        for (int kk = 0; kk < 4; kk++) {
            uint32_t kb = kk * 32;
            uint32_t ah[2][4], al[2][4], bh[4][4], bl[4][4];
            ldsm_x4(ah[0], aab + kb);
            ldsm_x4(ah[1], aab + MT_STRIDE_B + kb);
            ldsm_x4(al[0], aab + LO_OFF_B + kb);
            ldsm_x4(al[1], aab + LO_OFF_B + MT_STRIDE_B + kb);
#pragma unroll
            for (int q = 0; q < 4; q++) {
                ldsm_x4(bh[q], bab + q * MT_STRIDE_B + kb);
                ldsm_x4(bl[q], bab + LO_OFF_B + q * MT_STRIDE_B + kb);
            }
#pragma unroll
            for (int nt = 0; nt < 8; nt++) {
                int p = nt >> 1, sl = nt & 1;
                uint32_t b0h = bh[p][sl], b1h = bh[p][2 + sl];
                uint32_t b0l = bl[p][sl], b1l = bl[p][2 + sl];
#pragma unroll
                for (int mt = 0; mt < 2; mt++) {
                    mma_bf16(acc[mt][nt][0], acc[mt][nt][1], acc[mt][nt][2], acc[mt][nt][3],
                             ah[mt][0], ah[mt][1], ah[mt][2], ah[mt][3], b0h, b1h);
                    mma_bf16(acc[mt][nt][0], acc[mt][nt][1], acc[mt][nt][2], acc[mt][nt][3],
                             ah[mt][0], ah[mt][1], ah[mt][2], ah[mt][3], b0l, b1l);
                    mma_bf16(acc[mt][nt][0], acc[mt][nt][1], acc[mt][nt][2], acc[mt][nt][3],
                             al[mt][0], al[mt][1], al[mt][2], al[mt][3], b0h, b1h);
                }
            }
        }
    }

    const float* a1 = a + e * 2 * DD;
    const float* a2 = a1 + DD;
#pragma unroll
    for (int mt = 0; mt < 2; mt++) {
#pragma unroll
        for (int half = 0; half < 2; half++) {
            int row_local = warpM + mt * 16 + half * 8 + g;
            int n = n0 + row_local;
            float p1 = 0.f, p2 = 0.f;
#pragma unroll
            for (int nt = 0; nt < 8; nt++) {
                int col = warpN + nt * 8 + 2 * th;
                float c0 = acc[mt][nt][half * 2];
                float c1 = acc[mt][nt][half * 2 + 1];
                p1 += c0 * __ldg(a1 + col) + c1 * __ldg(a1 + col + 1);
                p2 += c0 * __ldg(a2 + col) + c1 * __ldg(a2 + col + 1);
                if (n < NN)
                    *(__half2*)&d_hh[((size_t)n * NEV + e) * DD + col] = __floats2half2_rn(c0, c1);
            }
            p1 += __shfl_xor_sync(0xffffffffu, p1, 1);
            p1 += __shfl_xor_sync(0xffffffffu, p1, 2);
            p2 += __shfl_xor_sync(0xffffffffu, p2, 1);
            p2 += __shfl_xor_sync(0xffffffffu, p2, 2);
            if (th == 0) {
                atomicAdd(&s1r[row_local], p1);   // exactly 2 adds/addr -> deterministic
                atomicAdd(&s2r[row_local], p2);
            }
        }
    }
    __syncthreads();
    if (t < 128) {
        int n = n0 + t;
        if (n < NN) {
            d_ssrc[n * NEV + e] = s1r[t];
            d_sdst[n * NEV + e] = s2r[t];
        }
    }
}

// ---------------- histogram of src degrees ----------------
__global__ void hist_kernel(const int* __restrict__ adj) {
    int i = blockIdx.x * blockDim.x + threadIdx.x;
    if (i < EE) atomicAdd(&d_cnt[adj[i]], 1);
}

// ---------------- multi-block scan: stage 1 (local scan + block totals) ----------------
__global__ void blockscan_kernel() {
    __shared__ int wsum[8];
    int blk = blockIdx.x, t = threadIdx.x, lane = t & 31, w = t >> 5;
    int i = blk * 256 + t;
    int v = (i < NN) ? d_cnt[i] : 0;
    int s = v;
#pragma unroll
    for (int o = 1; o < 32; o <<= 1) {
        int y = __shfl_up_sync(0xffffffffu, s, o);
        if (lane >= o) s += y;
    }
    if (lane == 31) wsum[w] = s;
    __syncthreads();
    if (t == 0) {
        int acc = 0;
#pragma unroll
        for (int j = 0; j < 8; j++) { int x = wsum[j]; wsum[j] = acc; acc += x; }
        d_bsum[blk] = acc;
    }
    __syncthreads();
    if (i < NN) d_off[i] = wsum[w] + s - v;   // exclusive within block
}

// ---------------- scan stage 2: scan the 196 block totals (one small block) ----------------
__global__ void bscan2_kernel() {
    __shared__ int wsum[8];
    int t = threadIdx.x, lane = t & 31, w = t >> 5;
    int v = (t < NBLK) ? d_bsum[t] : 0;
    int s = v;
#pragma unroll
    for (int o = 1; o < 32; o <<= 1) {
        int y = __shfl_up_sync(0xffffffffu, s, o);
        if (lane >= o) s += y;
    }
    if (lane == 31) wsum[w] = s;
    __syncthreads();
    if (t == 0) {
        int acc = 0;
#pragma unroll
        for (int j = 0; j < 8; j++) { int x = wsum[j]; wsum[j] = acc; acc += x; }
    }
    __syncthreads();
    if (t < NBLK) d_boff[t] = wsum[w] + s - v;
}

// ---------------- scan stage 3: add block offsets, init cursors ----------------
__global__ void addoff_kernel() {
    int i = blockIdx.x * blockDim.x + threadIdx.x;
    if (i < NN) {
        int o = d_off[i] + d_boff[blockIdx.x];
        d_off[i] = o;
        d_cur[i] = o;
    }
    if (i == 0) d_off[NN] = EE;
}

// ---------------- merged scatter + global per-env max ----------------
__global__ void scatter_max_kernel(const int* __restrict__ adj) {
    const int tot = EE + NN;
    float lm[NEV];
#pragma unroll
    for (int e = 0; e < NEV; e++) lm[e] = -1e30f;

    int stride = gridDim.x * blockDim.x;
    for (int i = blockIdx.x * blockDim.x + threadIdx.x; i < tot; i += stride) {
        int s, d;
        if (i < EE) {
            s = adj[i]; d = adj[EE + i];
            int p = atomicAdd(&d_cur[s], 1);
            d_csr[p] = d;
        } else {
            s = i - EE; d = s;
        }
#pragma unroll
        for (int e = 0; e < NEV; e++) {
            float v = lrelu(d_ssrc[s * NEV + e] + d_sdst[d * NEV + e]);
            lm[e] = fmaxf(lm[e], v);
        }
    }
#pragma unroll
    for (int o = 16; o > 0; o >>= 1)
#pragma unroll
        for (int e = 0; e < NEV; e++)
            lm[e] = fmaxf(lm[e], __shfl_xor_sync(0xffffffffu, lm[e], o));

    __shared__ float red[NEV][8];
    int lane = threadIdx.x & 31, wrp = threadIdx.x >> 5;
    if (lane == 0)
#pragma unroll
        for (int e = 0; e < NEV; e++) red[e][wrp] = lm[e];
    __syncthreads();
    if (wrp == 0) {
#pragma unroll
        for (int e = 0; e < NEV; e++) {
            float v = (lane < 8) ? red[e][lane] : -1e30f;
#pragma unroll
            for (int o = 4; o > 0; o >>= 1)
                v = fmaxf(v, __shfl_xor_sync(0xffffffffu, v, o));
            if (lane == 0) atomicMax(&d_maxu[e], fenc(v));
        }
    }
}

// ---------------- aggregate: one warp per node, fp16 h reads, fused final combine ----------------
__global__ void agg_kernel(const float* __restrict__ x,
                           const float* __restrict__ envw,
                           float* __restrict__ out) {
    int wid  = (blockIdx.x * blockDim.x + threadIdx.x) >> 5;
    int lane = threadIdx.x & 31;
    if (wid >= NN) return;
    int n = wid;

    float m[NEV], ss[NEV];
#pragma unroll
    for (int e = 0; e < NEV; e++) {
        m[e]  = fdec(d_maxu[e]);
        ss[e] = d_ssrc[n * NEV + e];
    }
    float4 sdn = *(const float4*)&d_sdst[n * NEV];
    float sdv[NEV] = {sdn.x, sdn.y, sdn.z, sdn.w};

    float acc[NEV][4];
    float den[NEV];

    // self loop
#pragma unroll
    for (int e = 0; e < NEV; e++) {
        float wv = __expf(lrelu(ss[e] + sdv[e]) - m[e]);
        den[e] = wv;
        uint2 u = *(const uint2*)&d_hh[((size_t)n * NEV + e) * DD + lane * 4];
        float2 f0 = __half22float2(*(__half2*)&u.x);
        float2 f1 = __half22float2(*(__half2*)&u.y);
        acc[e][0] = wv * f0.x; acc[e][1] = wv * f0.y;
        acc[e][2] = wv * f1.x; acc[e][3] = wv * f1.y;
    }

    int start = d_off[n], end = d_off[n + 1];
    int e_l = lane & 3, j_l = lane >> 2;
    float ss_l = ss[e_l], m_l = m[e_l];

    for (int base = start; base < end; base += 8) {
        int idx = base + j_l;
        int dl = 0;
        float wl = 0.f;
        if (idx < end) {
            dl = d_csr[idx];
            float sv = d_sdst[dl * NEV + e_l];
            wl = __expf(lrelu(ss_l + sv) - m_l);
        }
        int cnt = end - base; if (cnt > 8) cnt = 8;
#pragma unroll
        for (int j = 0; j < 8; j++) {
            if (j >= cnt) break;
            int d = __shfl_sync(0xffffffffu, dl, j * 4);
            const __half* hp = d_hh + (size_t)d * NEV * DD + lane * 4;
#pragma unroll
            for (int e = 0; e < NEV; e++) {
                float wv = __shfl_sync(0xffffffffu, wl, j * 4 + e);
                uint2 u = *(const uint2*)(hp + e * DD);
                float2 f0 = __half22float2(*(__half2*)&u.x);
                float2 f1 = __half22float2(*(__half2*)&u.y);
                den[e] += wv;
                acc[e][0] += wv * f0.x; acc[e][1] += wv * f0.y;
                acc[e][2] += wv * f1.x; acc[e][3] += wv * f1.y;
            }
        }
    }

    float4 ew = *(const float4*)&envw[n * NEV];
    float ewv[NEV] = {ew.x, ew.y, ew.z, ew.w};
    float4 xv = *(const float4*)&x[(size_t)n * DD + lane * 4];
    float o0 = xv.x, o1 = xv.y, o2 = xv.z, o3 = xv.w;
#pragma unroll
    for (int e = 0; e < NEV; e++) {
        float c = ewv[e] / (den[e] + EPSV);
        o0 += c * acc[e][0]; o1 += c * acc[e][1];
        o2 += c * acc[e][2]; o3 += c * acc[e][3];
    }
    *(float4*)&out[(size_t)n * DD + lane * 4] = make_float4(o0, o1, o2, o3);
}

// ---------------- launcher ----------------
extern "C" void kernel_launch(void* const* d_in, const int* in_sizes, int n_in,
                              void* d_out, int out_size) {
    const float* x    = (const float*)d_in[0];
    const int*   adj  = (const int*)d_in[1];
    const float* envw = (const float*)d_in[2];
    const float* W    = (const float*)d_in[3];
    const float* a    = (const float*)d_in[4];
    float* out = (float*)d_out;

    cudaFuncSetAttribute(gemm_kernel, cudaFuncAttributeMaxDynamicSharedMemorySize, SMEM_BYTES);

    prep_kernel<<<(NEV * DD * DD + 255) / 256, 256>>>(W);
    hist_kernel<<<(EE + 255) / 256, 256>>>(adj);
    blockscan_kernel<<<NBLK, 256>>>();
    bscan2_kernel<<<1, 256>>>();
    addoff_kernel<<<NBLK, 256>>>();
    gemm_kernel<<<dim3((NN + 127) / 128, NEV), 256, SMEM_BYTES>>>(x, a);
    scatter_max_kernel<<<1024, 256>>>(adj);
    agg_kernel<<<(NN + 7) / 8, 256>>>(x, envw, out);
}

// round 10
// speedup vs baseline: 1.9321x; 1.0348x over previous
#include <cuda_runtime.h>
#include <cuda_bf16.h>
#include <cuda_fp16.h>
#include <cstdint>

#define NN 50000
#define EE 800000
#define DD 128
#define NEV 4
#define EPSV 1e-8f
#define NBLK ((NN + 255) / 256)   // 196

// ---------------- scratch (device globals; no allocation allowed) ----------------
__device__ __half d_hh[(size_t)NN * NEV * DD];   // [n][e][f] fp16, 51.2 MB
__device__ float d_ssrc[NN * NEV];
__device__ float d_sdst[NN * NEV];
__device__ unsigned d_max1u[NEV];   // ordered-uint encoded max_n ssrc[n][e]
__device__ unsigned d_max2u[NEV];   // ordered-uint encoded max_n sdst[n][e]
__device__ int d_cnt[NN];
__device__ int d_off[NN + 1];
__device__ int d_cur[NN];
__device__ int d_csr[EE];
__device__ int d_bsum[NBLK];
__device__ __nv_bfloat16 d_Wth[NEV * DD * DD];   // W^T hi: [e][f][k]
__device__ __nv_bfloat16 d_Wtl[NEV * DD * DD];   // W^T lo

__device__ __forceinline__ unsigned fenc(float f) {
    unsigned u = __float_as_uint(f);
    return (u & 0x80000000u) ? ~u : (u | 0x80000000u);
}
__device__ __forceinline__ float fdec(unsigned u) {
    u = (u & 0x80000000u) ? (u & 0x7fffffffu) : ~u;
    return __uint_as_float(u);
}
__device__ __forceinline__ float lrelu(float v) { return v > 0.f ? v : 0.01f * v; }

__device__ __forceinline__ uint32_t pack_bf2(float lo, float hi) {
    __nv_bfloat162 p;
    p.x = __float2bfloat16(lo);
    p.y = __float2bfloat16(hi);
    return *(uint32_t*)&p;
}

__device__ __forceinline__ void mma_bf16(float& c0, float& c1, float& c2, float& c3,
                                         uint32_t a0, uint32_t a1, uint32_t a2, uint32_t a3,
                                         uint32_t b0, uint32_t b1) {
    asm volatile(
        "mma.sync.aligned.m16n8k16.row.col.f32.bf16.bf16.f32 "
        "{%0,%1,%2,%3}, {%4,%5,%6,%7}, {%8,%9}, {%0,%1,%2,%3};\n"
        : "+f"(c0), "+f"(c1), "+f"(c2), "+f"(c3)
        : "r"(a0), "r"(a1), "r"(a2), "r"(a3), "r"(b0), "r"(b1));
}

__device__ __forceinline__ void ldsm_x4(uint32_t* r, uint32_t addr) {
    asm volatile("ldmatrix.sync.aligned.m8n8.x4.shared.b16 {%0,%1,%2,%3}, [%4];"
                 : "=r"(r[0]), "=r"(r[1]), "=r"(r[2]), "=r"(r[3]) : "r"(addr));
}

// smem layout (word offsets), K staged in halves of 64.
#define ROWW 36
#define AH_W 0
#define AL_W (128 * ROWW)
#define BH_W (2 * 128 * ROWW)
#define BL_W (3 * 128 * ROWW)
#define SRED_W (4 * 128 * ROWW)
#define SMEM_WORDS (SRED_W + 256)
#define SMEM_BYTES (SMEM_WORDS * 4)
#define MT_STRIDE_B (16 * ROWW * 4)
#define LO_OFF_B (128 * ROWW * 4)

// ---------------- init + W prep (merged) ----------------
__global__ void prep_kernel(const float* __restrict__ W) {
    int i = blockIdx.x * blockDim.x + threadIdx.x;
    if (i < NN) d_cnt[i] = 0;
    if (i < NEV) { d_max1u[i] = 0u; d_max2u[i] = 0u; }
    if (i < NEV * DD * DD) {
        int e = i >> 14;
        int k = (i >> 7) & 127;
        int f = i & 127;
        float v = W[i];
        __nv_bfloat16 hb = __float2bfloat16(v);
        __nv_bfloat16 lb = __float2bfloat16(v - __bfloat162float(hb));
        int o = ((e * DD + f) << 7) + k;
        d_Wth[o] = hb;
        d_Wtl[o] = lb;
    }
}

// ---------------- GEMM: h = x @ W_e via mma.sync bf16x3 + ldmatrix, fused s + node max ----------------
__global__ void __launch_bounds__(256, 2) gemm_kernel(const float* __restrict__ x,
                                                      const float* __restrict__ a) {
    extern __shared__ uint32_t sm[];
    uint32_t smb = (uint32_t)__cvta_generic_to_shared(sm);
    int t = threadIdx.x, lane = t & 31, wid = t >> 5;
    int e = blockIdx.y;
    int n0 = blockIdx.x * 128;

    float* s1r = (float*)(sm + SRED_W);
    float* s2r = s1r + 128;
    if (t < 128) { s1r[t] = 0.f; s2r[t] = 0.f; }

    int warpM = (wid >> 1) * 32;
    int warpN = (wid & 1) * 64;
    int g = lane >> 2, th = lane & 3;
    int lrow = lane & 15, lhalf = lane >> 4;

    uint32_t aab = smb + (uint32_t)(AH_W + (warpM + lrow) * ROWW + lhalf * 4) * 4;
    uint32_t bab = smb + (uint32_t)(BH_W + (warpN + lrow) * ROWW + lhalf * 4) * 4;

    float acc[2][8][4];
#pragma unroll
    for (int mt = 0; mt < 2; mt++)
#pragma unroll
        for (int nt = 0; nt < 8; nt++)
#pragma unroll
            for (int j = 0; j < 4; j++) acc[mt][nt][j] = 0.f;

    const float4* x4 = (const float4*)x;
    const uint2* wh2 = (const uint2*)(d_Wth + e * DD * DD);
    const uint2* wl2 = (const uint2*)(d_Wtl + e * DD * DD);

#pragma unroll
    for (int s = 0; s < 2; s++) {
        if (s) __syncthreads();

#pragma unroll
        for (int i = 0; i < 8; i++) {
            int q = i * 256 + t;
            int row = q >> 4;
            int c4 = q & 15;
            float4 v = make_float4(0.f, 0.f, 0.f, 0.f);
            int n = n0 + row;
            if (n < NN) v = x4[(size_t)n * 32 + s * 16 + c4];
            float h0 = __bfloat162float(__float2bfloat16(v.x));
            float h1 = __bfloat162float(__float2bfloat16(v.y));
            float h2 = __bfloat162float(__float2bfloat16(v.z));
            float h3 = __bfloat162float(__float2bfloat16(v.w));
            uint2 hv, lv;
            hv.x = pack_bf2(v.x, v.y); hv.y = pack_bf2(v.z, v.w);
            lv.x = pack_bf2(v.x - h0, v.y - h1); lv.y = pack_bf2(v.z - h2, v.w - h3);
            *(uint2*)(sm + AH_W + row * ROWW + 2 * c4) = hv;
            *(uint2*)(sm + AL_W + row * ROWW + 2 * c4) = lv;
        }
#pragma unroll
        for (int i = 0; i < 8; i++) {
            int q = i * 256 + t;
            int row = q >> 4;
            int kq = q & 15;
            *(uint2*)(sm + BH_W + row * ROWW + 2 * kq) = wh2[row * 32 + s * 16 + kq];
            *(uint2*)(sm + BL_W + row * ROWW + 2 * kq) = wl2[row * 32 + s * 16 + kq];
        }
        __syncthreads();

#pragma unroll
        for (int kk = 0; kk < 4; kk++) {
            uint32_t kb = kk * 32;
            uint32_t ah[2][4], al[2][4], bh[4][4], bl[4][4];
            ldsm_x4(ah[0], aab + kb);
            ldsm_x4(ah[1], aab + MT_STRIDE_B + kb);
            ldsm_x4(al[0], aab + LO_OFF_B + kb);
            ldsm_x4(al[1], aab + LO_OFF_B + MT_STRIDE_B + kb);
#pragma unroll
            for (int q = 0; q < 4; q++) {
                ldsm_x4(bh[q], bab + q * MT_STRIDE_B + kb);
                ldsm_x4(bl[q], bab + LO_OFF_B + q * MT_STRIDE_B + kb);
            }
#pragma unroll
            for (int nt = 0; nt < 8; nt++) {
                int p = nt >> 1, sl = nt & 1;
                uint32_t b0h = bh[p][sl], b1h = bh[p][2 + sl];
                uint32_t b0l = bl[p][sl], b1l = bl[p][2 + sl];
#pragma unroll
                for (int mt = 0; mt < 2; mt++) {
                    mma_bf16(acc[mt][nt][0], acc[mt][nt][1], acc[mt][nt][2], acc[mt][nt][3],
                             ah[mt][0], ah[mt][1], ah[mt][2], ah[mt][3], b0h, b1h);
                    mma_bf16(acc[mt][nt][0], acc[mt][nt][1], acc[mt][nt][2], acc[mt][nt][3],
                             ah[mt][0], ah[mt][1], ah[mt][2], ah[mt][3], b0l, b1l);
                    mma_bf16(acc[mt][nt][0], acc[mt][nt][1], acc[mt][nt][2], acc[mt][nt][3],
                             al[mt][0], al[mt][1], al[mt][2], al[mt][3], b0h, b1h);
                }
            }
        }
    }

    const float* a1 = a + e * 2 * DD;
    const float* a2 = a1 + DD;
#pragma unroll
    for (int mt = 0; mt < 2; mt++) {
#pragma unroll
        for (int half = 0; half < 2; half++) {
            int row_local = warpM + mt * 16 + half * 8 + g;
            int n = n0 + row_local;
            float p1 = 0.f, p2 = 0.f;
#pragma unroll
            for (int nt = 0; nt < 8; nt++) {
                int col = warpN + nt * 8 + 2 * th;
                float c0 = acc[mt][nt][half * 2];
                float c1 = acc[mt][nt][half * 2 + 1];
                p1 += c0 * __ldg(a1 + col) + c1 * __ldg(a1 + col + 1);
                p2 += c0 * __ldg(a2 + col) + c1 * __ldg(a2 + col + 1);
                if (n < NN)
                    *(__half2*)&d_hh[((size_t)n * NEV + e) * DD + col] = __floats2half2_rn(c0, c1);
            }
            p1 += __shfl_xor_sync(0xffffffffu, p1, 1);
            p1 += __shfl_xor_sync(0xffffffffu, p1, 2);
            p2 += __shfl_xor_sync(0xffffffffu, p2, 1);
            p2 += __shfl_xor_sync(0xffffffffu, p2, 2);
            if (th == 0) {
                atomicAdd(&s1r[row_local], p1);   // exactly 2 adds/addr -> deterministic
                atomicAdd(&s2r[row_local], p2);
            }
        }
    }
    __syncthreads();
    if (t < 128) {
        int n = n0 + t;
        float v1 = s1r[t], v2 = s2r[t];
        bool ok = (n < NN);
        if (ok) {
            d_ssrc[n * NEV + e] = v1;
            d_sdst[n * NEV + e] = v2;
        } else {
            v1 = -1e30f; v2 = -1e30f;
        }
        // warp-level node max -> 2 atomics/warp (8/block) for the softmax bound
#pragma unroll
        for (int o = 16; o > 0; o >>= 1) {
            v1 = fmaxf(v1, __shfl_xor_sync(0xffffffffu, v1, o));
            v2 = fmaxf(v2, __shfl_xor_sync(0xffffffffu, v2, o));
        }
        if (lane == 0) {
            atomicMax(&d_max1u[e], fenc(v1));
            atomicMax(&d_max2u[e], fenc(v2));
        }
    }
}

// ---------------- histogram of src degrees ----------------
__global__ void hist_kernel(const int* __restrict__ adj) {
    int i = blockIdx.x * blockDim.x + threadIdx.x;
    if (i < EE) atomicAdd(&d_cnt[adj[i]], 1);
}

// ---------------- multi-block scan: stage 1 (local scan + block totals) ----------------
__global__ void blockscan_kernel() {
    __shared__ int wsum[8];
    int blk = blockIdx.x, t = threadIdx.x, lane = t & 31, w = t >> 5;
    int i = blk * 256 + t;
    int v = (i < NN) ? d_cnt[i] : 0;
    int s = v;
#pragma unroll
    for (int o = 1; o < 32; o <<= 1) {
        int y = __shfl_up_sync(0xffffffffu, s, o);
        if (lane >= o) s += y;
    }
    if (lane == 31) wsum[w] = s;
    __syncthreads();
    if (t == 0) {
        int acc = 0;
#pragma unroll
        for (int j = 0; j < 8; j++) { int x = wsum[j]; wsum[j] = acc; acc += x; }
        d_bsum[blk] = acc;
    }
    __syncthreads();
    if (i < NN) d_off[i] = wsum[w] + s - v;   // exclusive within block
}

// ---------------- scan stage 2: each block sums its predecessor totals + adds ----------------
__global__ void addoff_kernel() {
    __shared__ int wsum[8];
    __shared__ int s_boff;
    int t = threadIdx.x, lane = t & 31, w = t >> 5;
    int blk = blockIdx.x;
    // reduce d_bsum[0..blk)
    int v = (t < blk) ? d_bsum[t] : 0;    // NBLK=196 <= 256
#pragma unroll
    for (int o = 16; o > 0; o >>= 1) v += __shfl_xor_sync(0xffffffffu, v, o);
    if (lane == 0) wsum[w] = v;
    __syncthreads();
    if (t == 0) {
        int acc = 0;
#pragma unroll
        for (int j = 0; j < 8; j++) acc += wsum[j];
        s_boff = acc;
    }
    __syncthreads();
    int i = blk * 256 + t;
    if (i < NN) {
        int o = d_off[i] + s_boff;
        d_off[i] = o;
        d_cur[i] = o;
    }
    if (i == 0) d_off[NN] = EE;
}

// ---------------- pure scatter into CSR groups ----------------
__global__ void scatter_kernel(const int* __restrict__ adj) {
    int i = blockIdx.x * blockDim.x + threadIdx.x;
    if (i < EE) {
        int s = adj[i];
        int d = adj[EE + i];
        int p = atomicAdd(&d_cur[s], 1);
        d_csr[p] = d;
    }
}

// ---------------- aggregate: one warp per node, fp16 h reads, fused final combine ----------------
__global__ void agg_kernel(const float* __restrict__ x,
                           const float* __restrict__ envw,
                           float* __restrict__ out) {
    int wid  = (blockIdx.x * blockDim.x + threadIdx.x) >> 5;
    int lane = threadIdx.x & 31;
    if (wid >= NN) return;
    int n = wid;

    float m[NEV], ss[NEV];
#pragma unroll
    for (int e = 0; e < NEV; e++) {
        // softmax bound: m >= true max logit; exact value cancels in num/denom
        m[e]  = lrelu(fdec(d_max1u[e]) + fdec(d_max2u[e]));
        ss[e] = d_ssrc[n * NEV + e];
    }
    float4 sdn = *(const float4*)&d_sdst[n * NEV];
    float sdv[NEV] = {sdn.x, sdn.y, sdn.z, sdn.w};

    float acc[NEV][4];
    float den[NEV];

    // self loop
#pragma unroll
    for (int e = 0; e < NEV; e++) {
        float wv = __expf(lrelu(ss[e] + sdv[e]) - m[e]);
        den[e] = wv;
        uint2 u = *(const uint2*)&d_hh[((size_t)n * NEV + e) * DD + lane * 4];
        float2 f0 = __half22float2(*(__half2*)&u.x);
        float2 f1 = __half22float2(*(__half2*)&u.y);
        acc[e][0] = wv * f0.x; acc[e][1] = wv * f0.y;
        acc[e][2] = wv * f1.x; acc[e][3] = wv * f1.y;
    }

    int start = d_off[n], end = d_off[n + 1];
    int e_l = lane & 3, j_l = lane >> 2;
    float ss_l = ss[e_l], m_l = m[e_l];

    for (int base = start; base < end; base += 8) {
        int idx = base + j_l;
        int dl = 0;
        float wl = 0.f;
        if (idx < end) {
            dl = d_csr[idx];
            float sv = d_sdst[dl * NEV + e_l];
            wl = __expf(lrelu(ss_l + sv) - m_l);
        }
        int cnt = end - base; if (cnt > 8) cnt = 8;
#pragma unroll
        for (int j = 0; j < 8; j++) {
            if (j >= cnt) break;
            int d = __shfl_sync(0xffffffffu, dl, j * 4);
            const __half* hp = d_hh + (size_t)d * NEV * DD + lane * 4;
#pragma unroll
            for (int e = 0; e < NEV; e++) {
                float wv = __shfl_sync(0xffffffffu, wl, j * 4 + e);
                uint2 u = *(const uint2*)(hp + e * DD);
                float2 f0 = __half22float2(*(__half2*)&u.x);
                float2 f1 = __half22float2(*(__half2*)&u.y);
                den[e] += wv;
                acc[e][0] += wv * f0.x; acc[e][1] += wv * f0.y;
                acc[e][2] += wv * f1.x; acc[e][3] += wv * f1.y;
            }
        }
    }

    float4 ew = *(const float4*)&envw[n * NEV];
    float ewv[NEV] = {ew.x, ew.y, ew.z, ew.w};
    float4 xv = *(const float4*)&x[(size_t)n * DD + lane * 4];
    float o0 = xv.x, o1 = xv.y, o2 = xv.z, o3 = xv.w;
#pragma unroll
    for (int e = 0; e < NEV; e++) {
        float c = ewv[e] / (den[e] + EPSV);
        o0 += c * acc[e][0]; o1 += c * acc[e][1];
        o2 += c * acc[e][2]; o3 += c * acc[e][3];
    }
    *(float4*)&out[(size_t)n * DD + lane * 4] = make_float4(o0, o1, o2, o3);
}

// ---------------- launcher ----------------
extern "C" void kernel_launch(void* const* d_in, const int* in_sizes, int n_in,
                              void* d_out, int out_size) {
    const float* x    = (const float*)d_in[0];
    const int*   adj  = (const int*)d_in[1];
    const float* envw = (const float*)d_in[2];
    const float* W    = (const float*)d_in[3];
    const float* a    = (const float*)d_in[4];
    float* out = (float*)d_out;

    cudaFuncSetAttribute(gemm_kernel, cudaFuncAttributeMaxDynamicSharedMemorySize, SMEM_BYTES);

    prep_kernel<<<(NEV * DD * DD + 255) / 256, 256>>>(W);
    hist_kernel<<<(EE + 255) / 256, 256>>>(adj);
    blockscan_kernel<<<NBLK, 256>>>();
    addoff_kernel<<<NBLK, 256>>>();
    scatter_kernel<<<(EE + 255) / 256, 256>>>(adj);
    gemm_kernel<<<dim3((NN + 127) / 128, NEV), 256, SMEM_BYTES>>>(x, a);
    agg_kernel<<<(NN + 7) / 8, 256>>>(x, envw, out);
}

// round 13
// speedup vs baseline: 1.9341x; 1.0010x over previous
#include <cuda_runtime.h>
#include <cuda_bf16.h>
#include <cuda_fp16.h>
#include <cstdint>

#define NN 50000
#define EE 800000
#define DD 128
#define NEV 4
#define EPSV 1e-8f
#define NBLK ((NN + 255) / 256)      // 196
#define GEMM_BLKS (((NN + 127) / 128) * NEV)   // 391*4 = 1564
#define SCAT_BLKS ((EE + 255) / 256)           // 3125

// ---------------- scratch (device globals; no allocation allowed) ----------------
__device__ __half d_hh[(size_t)NN * NEV * DD];   // [n][e][f] fp16, 51.2 MB
__device__ __nv_bfloat16 d_xh[(size_t)NN * DD];  // x split hi
__device__ __nv_bfloat16 d_xl[(size_t)NN * DD];  // x split lo
__device__ float d_ssrc[NN * NEV];
__device__ float d_sdst[NN * NEV];
__device__ unsigned d_max1u[NEV];
__device__ unsigned d_max2u[NEV];
__device__ int d_cnt[NN];
__device__ int d_off[NN + 1];
__device__ int d_cur[NN];
__device__ int d_csr[EE];
__device__ int d_bsum[NBLK];
__device__ __nv_bfloat16 d_Wth[NEV * DD * DD];   // W^T hi: [e][f][k]
__device__ __nv_bfloat16 d_Wtl[NEV * DD * DD];   // W^T lo

__device__ __forceinline__ unsigned fenc(float f) {
    unsigned u = __float_as_uint(f);
    return (u & 0x80000000u) ? ~u : (u | 0x80000000u);
}
__device__ __forceinline__ float fdec(unsigned u) {
    u = (u & 0x80000000u) ? (u & 0x7fffffffu) : ~u;
    return __uint_as_float(u);
}
__device__ __forceinline__ float lrelu(float v) { return v > 0.f ? v : 0.01f * v; }

__device__ __forceinline__ uint32_t pack_bf2(float lo, float hi) {
    __nv_bfloat162 p;
    p.x = __float2bfloat16(lo);
    p.y = __float2bfloat16(hi);
    return *(uint32_t*)&p;
}

__device__ __forceinline__ void mma_bf16(float& c0, float& c1, float& c2, float& c3,
                                         uint32_t a0, uint32_t a1, uint32_t a2, uint32_t a3,
                                         uint32_t b0, uint32_t b1) {
    asm volatile(
        "mma.sync.aligned.m16n8k16.row.col.f32.bf16.bf16.f32 "
        "{%0,%1,%2,%3}, {%4,%5,%6,%7}, {%8,%9}, {%0,%1,%2,%3};\n"
        : "+f"(c0), "+f"(c1), "+f"(c2), "+f"(c3)
        : "r"(a0), "r"(a1), "r"(a2), "r"(a3), "r"(b0), "r"(b1));
}

__device__ __forceinline__ void ldsm_x4(uint32_t* r, uint32_t addr) {
    asm volatile("ldmatrix.sync.aligned.m8n8.x4.shared.b16 {%0,%1,%2,%3}, [%4];"
                 : "=r"(r[0]), "=r"(r[1]), "=r"(r[2]), "=r"(r[3]) : "r"(addr));
}

// smem layout (word offsets), K staged in halves of 64.
#define ROWW 36
#define AH_W 0
#define AL_W (128 * ROWW)
#define BH_W (2 * 128 * ROWW)
#define BL_W (3 * 128 * ROWW)
#define SRED_W (4 * 128 * ROWW)
#define SMEM_WORDS (SRED_W + 256)
#define SMEM_BYTES (SMEM_WORDS * 4)
#define MT_STRIDE_B (16 * ROWW * 4)
#define LO_OFF_B (128 * ROWW * 4)

// ---------------- tiny init: zero histogram + max accumulators ----------------
__global__ void zinit_kernel() {
    int i = blockIdx.x * blockDim.x + threadIdx.x;
    if (i < NN) d_cnt[i] = 0;
    if (i < NEV) { d_max1u[i] = 0u; d_max2u[i] = 0u; }
}

// ---------------- fused prep: x split || W split || histogram ----------------
__global__ void prep_kernel(const float* __restrict__ x,
                            const float* __restrict__ W,
                            const int* __restrict__ adj) {
    int i = blockIdx.x * blockDim.x + threadIdx.x;   // grid covers NN*32 = 1.6M
    if (i < NN * 32) {
        float4 v = ((const float4*)x)[i];
        float h0 = __bfloat162float(__float2bfloat16(v.x));
        float h1 = __bfloat162float(__float2bfloat16(v.y));
        float h2 = __bfloat162float(__float2bfloat16(v.z));
        float h3 = __bfloat162float(__float2bfloat16(v.w));
        uint2 hv, lv;
        hv.x = pack_bf2(v.x, v.y); hv.y = pack_bf2(v.z, v.w);
        lv.x = pack_bf2(v.x - h0, v.y - h1); lv.y = pack_bf2(v.z - h2, v.w - h3);
        ((uint2*)d_xh)[i] = hv;
        ((uint2*)d_xl)[i] = lv;
    }
    if (i < NEV * DD * DD) {
        int e = i >> 14;
        int k = (i >> 7) & 127;
        int f = i & 127;
        float v = W[i];
        __nv_bfloat16 hb = __float2bfloat16(v);
        __nv_bfloat16 lb = __float2bfloat16(v - __bfloat162float(hb));
        int o = ((e * DD + f) << 7) + k;
        d_Wth[o] = hb;
        d_Wtl[o] = lb;
    }
    if (i < EE) atomicAdd(&d_cnt[adj[i]], 1);
}

// ---------------- multi-block scan: stage 1 ----------------
__global__ void blockscan_kernel() {
    __shared__ int wsum[8];
    int blk = blockIdx.x, t = threadIdx.x, lane = t & 31, w = t >> 5;
    int i = blk * 256 + t;
    int v = (i < NN) ? d_cnt[i] : 0;
    int s = v;
#pragma unroll
    for (int o = 1; o < 32; o <<= 1) {
        int y = __shfl_up_sync(0xffffffffu, s, o);
        if (lane >= o) s += y;
    }
    if (lane == 31) wsum[w] = s;
    __syncthreads();
    if (t == 0) {
        int acc = 0;
#pragma unroll
        for (int j = 0; j < 8; j++) { int x = wsum[j]; wsum[j] = acc; acc += x; }
        d_bsum[blk] = acc;
    }
    __syncthreads();
    if (i < NN) d_off[i] = wsum[w] + s - v;
}

// ---------------- scan stage 2: per-block prefix + add ----------------
__global__ void addoff_kernel() {
    __shared__ int wsum[8];
    __shared__ int s_boff;
    int t = threadIdx.x, lane = t & 31, w = t >> 5;
    int blk = blockIdx.x;
    int v = (t < blk) ? d_bsum[t] : 0;    // NBLK=196 <= 256
#pragma unroll
    for (int o = 16; o > 0; o >>= 1) v += __shfl_xor_sync(0xffffffffu, v, o);
    if (lane == 0) wsum[w] = v;
    __syncthreads();
    if (t == 0) {
        int acc = 0;
#pragma unroll
        for (int j = 0; j < 8; j++) acc += wsum[j];
        s_boff = acc;
    }
    __syncthreads();
    int i = blk * 256 + t;
    if (i < NN) {
        int o = d_off[i] + s_boff;
        d_off[i] = o;
        d_cur[i] = o;
    }
    if (i == 0) d_off[NN] = EE;
}

// ---------------- fused GEMM (bf16x3 mma + ldmatrix, fused s + max) ∪ scatter ----------------
__global__ void __launch_bounds__(256, 2) gemm_scatter_kernel(const float* __restrict__ a,
                                                              const int* __restrict__ adj) {
    int bid = blockIdx.x;
    int t = threadIdx.x;

    if (bid >= GEMM_BLKS) {
        // ---------- scatter path (overlaps with gemm blocks on-chip) ----------
        int i = (bid - GEMM_BLKS) * 256 + t;
        if (i < EE) {
            int s = adj[i];
            int d = adj[EE + i];
            int p = atomicAdd(&d_cur[s], 1);
            d_csr[p] = d;
        }
        return;
    }

    // ---------- gemm path ----------
    extern __shared__ uint32_t sm[];
    uint32_t smb = (uint32_t)__cvta_generic_to_shared(sm);
    int lane = t & 31, wid = t >> 5;
    int e = bid & 3;
    int n0 = (bid >> 2) * 128;

    float* s1r = (float*)(sm + SRED_W);
    float* s2r = s1r + 128;
    if (t < 128) { s1r[t] = 0.f; s2r[t] = 0.f; }

    int warpM = (wid >> 1) * 32;
    int warpN = (wid & 1) * 64;
    int g = lane >> 2, th = lane & 3;
    int lrow = lane & 15, lhalf = lane >> 4;

    uint32_t aab = smb + (uint32_t)(AH_W + (warpM + lrow) * ROWW + lhalf * 4) * 4;
    uint32_t bab = smb + (uint32_t)(BH_W + (warpN + lrow) * ROWW + lhalf * 4) * 4;

    float acc[2][8][4];
#pragma unroll
    for (int mt = 0; mt < 2; mt++)
#pragma unroll
        for (int nt = 0; nt < 8; nt++)
#pragma unroll
            for (int j = 0; j < 4; j++) acc[mt][nt][j] = 0.f;

    const uint2* xh2 = (const uint2*)d_xh;
    const uint2* xl2 = (const uint2*)d_xl;
    const uint2* wh2 = (const uint2*)(d_Wth + e * DD * DD);
    const uint2* wl2 = (const uint2*)(d_Wtl + e * DD * DD);

#pragma unroll
    for (int s = 0; s < 2; s++) {
        if (s) __syncthreads();

        // ---- fill A half-tile from presplit x (pure copies) ----
#pragma unroll
        for (int i = 0; i < 8; i++) {
            int q = i * 256 + t;
            int row = q >> 4;
            int kq = q & 15;
            int n = n0 + row;
            uint2 hv = make_uint2(0u, 0u), lv = make_uint2(0u, 0u);
            if (n < NN) {
                hv = xh2[n * 32 + s * 16 + kq];
                lv = xl2[n * 32 + s * 16 + kq];
            }
            *(uint2*)(sm + AH_W + row * ROWW + 2 * kq) = hv;
            *(uint2*)(sm + AL_W + row * ROWW + 2 * kq) = lv;
        }
        // ---- fill B half-tile ----
#pragma unroll
        for (int i = 0; i < 8; i++) {
            int q = i * 256 + t;
            int row = q >> 4;
            int kq = q & 15;
            *(uint2*)(sm + BH_W + row * ROWW + 2 * kq) = wh2[row * 32 + s * 16 + kq];
            *(uint2*)(sm + BL_W + row * ROWW + 2 * kq) = wl2[row * 32 + s * 16 + kq];
        }
        __syncthreads();

#pragma unroll
        for (int kk = 0; kk < 4; kk++) {
            uint32_t kb = kk * 32;
            uint32_t ah[2][4], al[2][4], bh[4][4], bl[4][4];
            ldsm_x4(ah[0], aab + kb);
            ldsm_x4(ah[1], aab + MT_STRIDE_B + kb);
            ldsm_x4(al[0], aab + LO_OFF_B + kb);
            ldsm_x4(al[1], aab + LO_OFF_B + MT_STRIDE_B + kb);
#pragma unroll
            for (int q = 0; q < 4; q++) {
                ldsm_x4(bh[q], bab + q * MT_STRIDE_B + kb);
                ldsm_x4(bl[q], bab + LO_OFF_B + q * MT_STRIDE_B + kb);
            }
#pragma unroll
            for (int nt = 0; nt < 8; nt++) {
                int p = nt >> 1, sl = nt & 1;
                uint32_t b0h = bh[p][sl], b1h = bh[p][2 + sl];
                uint32_t b0l = bl[p][sl], b1l = bl[p][2 + sl];
#pragma unroll
                for (int mt = 0; mt < 2; mt++) {
                    mma_bf16(acc[mt][nt][0], acc[mt][nt][1], acc[mt][nt][2], acc[mt][nt][3],
                             ah[mt][0], ah[mt][1], ah[mt][2], ah[mt][3], b0h, b1h);
                    mma_bf16(acc[mt][nt][0], acc[mt][nt][1], acc[mt][nt][2], acc[mt][nt][3],
                             ah[mt][0], ah[mt][1], ah[mt][2], ah[mt][3], b0l, b1l);
                    mma_bf16(acc[mt][nt][0], acc[mt][nt][1], acc[mt][nt][2], acc[mt][nt][3],
                             al[mt][0], al[mt][1], al[mt][2], al[mt][3], b0h, b1h);
                }
            }
        }
    }

    const float* a1 = a + e * 2 * DD;
    const float* a2 = a1 + DD;
#pragma unroll
    for (int mt = 0; mt < 2; mt++) {
#pragma unroll
        for (int half = 0; half < 2; half++) {
            int row_local = warpM + mt * 16 + half * 8 + g;
            int n = n0 + row_local;
            float p1 = 0.f, p2 = 0.f;
#pragma unroll
            for (int nt = 0; nt < 8; nt++) {
                int col = warpN + nt * 8 + 2 * th;
                float c0 = acc[mt][nt][half * 2];
                float c1 = acc[mt][nt][half * 2 + 1];
                p1 += c0 * __ldg(a1 + col) + c1 * __ldg(a1 + col + 1);
                p2 += c0 * __ldg(a2 + col) + c1 * __ldg(a2 + col + 1);
                if (n < NN)
                    *(__half2*)&d_hh[((size_t)n * NEV + e) * DD + col] = __floats2half2_rn(c0, c1);
            }
            p1 += __shfl_xor_sync(0xffffffffu, p1, 1);
            p1 += __shfl_xor_sync(0xffffffffu, p1, 2);
            p2 += __shfl_xor_sync(0xffffffffu, p2, 1);
            p2 += __shfl_xor_sync(0xffffffffu, p2, 2);
            if (th == 0) {
                atomicAdd(&s1r[row_local], p1);   // exactly 2 adds/addr -> deterministic
                atomicAdd(&s2r[row_local], p2);
            }
        }
    }
    __syncthreads();
    if (t < 128) {
        int n = n0 + t;
        float v1 = s1r[t], v2 = s2r[t];
        bool ok = (n < NN);
        if (ok) {
            d_ssrc[n * NEV + e] = v1;
            d_sdst[n * NEV + e] = v2;
        } else {
            v1 = -1e30f; v2 = -1e30f;
        }
#pragma unroll
        for (int o = 16; o > 0; o >>= 1) {
            v1 = fmaxf(v1, __shfl_xor_sync(0xffffffffu, v1, o));
            v2 = fmaxf(v2, __shfl_xor_sync(0xffffffffu, v2, o));
        }
        if (lane == 0) {
            atomicMax(&d_max1u[e], fenc(v1));
            atomicMax(&d_max2u[e], fenc(v2));
        }
    }
}

// ---------------- aggregate: one warp per node, fp16 h reads, fused final combine ----------------
__global__ void agg_kernel(const float* __restrict__ x,
                           const float* __restrict__ envw,
                           float* __restrict__ out) {
    int wid  = (blockIdx.x * blockDim.x + threadIdx.x) >> 5;
    int lane = threadIdx.x & 31;
    if (wid >= NN) return;
    int n = wid;

    float m[NEV], ss[NEV];
#pragma unroll
    for (int e = 0; e < NEV; e++) {
        // softmax bound: m >= true max logit; exact value cancels in num/denom
        m[e]  = lrelu(fdec(d_max1u[e]) + fdec(d_max2u[e]));
        ss[e] = d_ssrc[n * NEV + e];
    }
    float4 sdn = *(const float4*)&d_sdst[n * NEV];
    float sdv[NEV] = {sdn.x, sdn.y, sdn.z, sdn.w};

    float acc[NEV][4];
    float den[NEV];

    // self loop
#pragma unroll
    for (int e = 0; e < NEV; e++) {
        float wv = __expf(lrelu(ss[e] + sdv[e]) - m[e]);
        den[e] = wv;
        uint2 u = *(const uint2*)&d_hh[((size_t)n * NEV + e) * DD + lane * 4];
        float2 f0 = __half22float2(*(__half2*)&u.x);
        float2 f1 = __half22float2(*(__half2*)&u.y);
        acc[e][0] = wv * f0.x; acc[e][1] = wv * f0.y;
        acc[e][2] = wv * f1.x; acc[e][3] = wv * f1.y;
    }

    int start = d_off[n], end = d_off[n + 1];
    int e_l = lane & 3, j_l = lane >> 2;
    float ss_l = ss[e_l], m_l = m[e_l];

    for (int base = start; base < end; base += 8) {
        int idx = base + j_l;
        int dl = 0;
        float wl = 0.f;
        if (idx < end) {
            dl = d_csr[idx];
            float sv = d_sdst[dl * NEV + e_l];
            wl = __expf(lrelu(ss_l + sv) - m_l);
        }
        int cnt = end - base; if (cnt > 8) cnt = 8;
#pragma unroll
        for (int j = 0; j < 8; j++) {
            if (j >= cnt) break;
            int d = __shfl_sync(0xffffffffu, dl, j * 4);
            const __half* hp = d_hh + (size_t)d * NEV * DD + lane * 4;
#pragma unroll
            for (int e = 0; e < NEV; e++) {
                float wv = __shfl_sync(0xffffffffu, wl, j * 4 + e);
                uint2 u = *(const uint2*)(hp + e * DD);
                float2 f0 = __half22float2(*(__half2*)&u.x);
                float2 f1 = __half22float2(*(__half2*)&u.y);
                den[e] += wv;
                acc[e][0] += wv * f0.x; acc[e][1] += wv * f0.y;
                acc[e][2] += wv * f1.x; acc[e][3] += wv * f1.y;
            }
        }
    }

    float4 ew = *(const float4*)&envw[n * NEV];
    float ewv[NEV] = {ew.x, ew.y, ew.z, ew.w};
    float4 xv = *(const float4*)&x[(size_t)n * DD + lane * 4];
    float o0 = xv.x, o1 = xv.y, o2 = xv.z, o3 = xv.w;
#pragma unroll
    for (int e = 0; e < NEV; e++) {
        float c = ewv[e] / (den[e] + EPSV);
        o0 += c * acc[e][0]; o1 += c * acc[e][1];
        o2 += c * acc[e][2]; o3 += c * acc[e][3];
    }
    *(float4*)&out[(size_t)n * DD + lane * 4] = make_float4(o0, o1, o2, o3);
}

// ---------------- launcher ----------------
extern "C" void kernel_launch(void* const* d_in, const int* in_sizes, int n_in,
                              void* d_out, int out_size) {
    const float* x    = (const float*)d_in[0];
    const int*   adj  = (const int*)d_in[1];
    const float* envw = (const float*)d_in[2];
    const float* W    = (const float*)d_in[3];
    const float* a    = (const float*)d_in[4];
    float* out = (float*)d_out;

    cudaFuncSetAttribute(gemm_scatter_kernel, cudaFuncAttributeMaxDynamicSharedMemorySize, SMEM_BYTES);

    zinit_kernel<<<NBLK, 256>>>();
    prep_kernel<<<(NN * 32 + 255) / 256, 256>>>(x, W, adj);
    blockscan_kernel<<<NBLK, 256>>>();
    addoff_kernel<<<NBLK, 256>>>();
    gemm_scatter_kernel<<<GEMM_BLKS + SCAT_BLKS, 256, SMEM_BYTES>>>(a, adj);
    agg_kernel<<<(NN + 7) / 8, 256>>>(x, envw, out);
}

// round 16
// speedup vs baseline: 2.0141x; 1.0413x over previous
#include <cuda_runtime.h>
#include <cuda_bf16.h>
#include <cuda_fp16.h>
#include <cstdint>

#define NN 50000
#define EE 800000
#define DD 128
#define NEV 4
#define EPSV 1e-8f
#define NBLK ((NN + 255) / 256)      // 196
#define GEMM_BLKS (((NN + 127) / 128) * NEV)   // 391*4 = 1564
#define SCAT_BLKS ((EE + 255) / 256)           // 3125

// ---------------- scratch (device globals; no allocation allowed) ----------------
__device__ __half d_hh[(size_t)NN * NEV * DD];   // [n][e][f] fp16, 51.2 MB
__device__ __nv_bfloat16 d_xh[(size_t)NN * DD];  // x split hi
__device__ __nv_bfloat16 d_xl[(size_t)NN * DD];  // x split lo
__device__ float d_ssrc[NN * NEV];
__device__ float d_sdst[NN * NEV];
__device__ unsigned d_max1u[NEV];
__device__ unsigned d_max2u[NEV];
__device__ int d_cnt[NN];
__device__ int d_off[NN + 1];
__device__ int d_cur[NN];
__device__ int d_csr[EE];
__device__ int d_bsum[NBLK];
__device__ __nv_bfloat16 d_Wth[NEV * DD * DD];   // W^T hi: [e][f][k]
__device__ __nv_bfloat16 d_Wtl[NEV * DD * DD];   // W^T lo

__device__ __forceinline__ unsigned fenc(float f) {
    unsigned u = __float_as_uint(f);
    return (u & 0x80000000u) ? ~u : (u | 0x80000000u);
}
__device__ __forceinline__ float fdec(unsigned u) {
    u = (u & 0x80000000u) ? (u & 0x7fffffffu) : ~u;
    return __uint_as_float(u);
}
__device__ __forceinline__ float lrelu(float v) { return v > 0.f ? v : 0.01f * v; }

__device__ __forceinline__ uint32_t pack_bf2(float lo, float hi) {
    __nv_bfloat162 p;
    p.x = __float2bfloat16(lo);
    p.y = __float2bfloat16(hi);
    return *(uint32_t*)&p;
}

__device__ __forceinline__ void unpack8(uint4 u, float* f) {
    float2 a = __half22float2(*(__half2*)&u.x);
    float2 b = __half22float2(*(__half2*)&u.y);
    float2 c = __half22float2(*(__half2*)&u.z);
    float2 d = __half22float2(*(__half2*)&u.w);
    f[0] = a.x; f[1] = a.y; f[2] = b.x; f[3] = b.y;
    f[4] = c.x; f[5] = c.y; f[6] = d.x; f[7] = d.y;
}

__device__ __forceinline__ void mma_bf16(float& c0, float& c1, float& c2, float& c3,
                                         uint32_t a0, uint32_t a1, uint32_t a2, uint32_t a3,
                                         uint32_t b0, uint32_t b1) {
    asm volatile(
        "mma.sync.aligned.m16n8k16.row.col.f32.bf16.bf16.f32 "
        "{%0,%1,%2,%3}, {%4,%5,%6,%7}, {%8,%9}, {%0,%1,%2,%3};\n"
        : "+f"(c0), "+f"(c1), "+f"(c2), "+f"(c3)
        : "r"(a0), "r"(a1), "r"(a2), "r"(a3), "r"(b0), "r"(b1));
}

__device__ __forceinline__ void ldsm_x4(uint32_t* r, uint32_t addr) {
    asm volatile("ldmatrix.sync.aligned.m8n8.x4.shared.b16 {%0,%1,%2,%3}, [%4];"
                 : "=r"(r[0]), "=r"(r[1]), "=r"(r[2]), "=r"(r[3]) : "r"(addr));
}

// smem layout (word offsets), K staged in halves of 64.
#define ROWW 36
#define AH_W 0
#define AL_W (128 * ROWW)
#define BH_W (2 * 128 * ROWW)
#define BL_W (3 * 128 * ROWW)
#define SRED_W (4 * 128 * ROWW)
#define SMEM_WORDS (SRED_W + 256)
#define SMEM_BYTES (SMEM_WORDS * 4)
#define MT_STRIDE_B (16 * ROWW * 4)
#define LO_OFF_B (128 * ROWW * 4)

// ---------------- tiny init: zero histogram + max accumulators ----------------
__global__ void zinit_kernel() {
    int i = blockIdx.x * blockDim.x + threadIdx.x;
    if (i < NN) d_cnt[i] = 0;
    if (i < NEV) { d_max1u[i] = 0u; d_max2u[i] = 0u; }
}

// ---------------- fused prep: x split || W split || histogram ----------------
__global__ void prep_kernel(const float* __restrict__ x,
                            const float* __restrict__ W,
                            const int* __restrict__ adj) {
    int i = blockIdx.x * blockDim.x + threadIdx.x;   // grid covers NN*32 = 1.6M
    if (i < NN * 32) {
        float4 v = ((const float4*)x)[i];
        float h0 = __bfloat162float(__float2bfloat16(v.x));
        float h1 = __bfloat162float(__float2bfloat16(v.y));
        float h2 = __bfloat162float(__float2bfloat16(v.z));
        float h3 = __bfloat162float(__float2bfloat16(v.w));
        uint2 hv, lv;
        hv.x = pack_bf2(v.x, v.y); hv.y = pack_bf2(v.z, v.w);
        lv.x = pack_bf2(v.x - h0, v.y - h1); lv.y = pack_bf2(v.z - h2, v.w - h3);
        ((uint2*)d_xh)[i] = hv;
        ((uint2*)d_xl)[i] = lv;
    }
    if (i < NEV * DD * DD) {
        int e = i >> 14;
        int k = (i >> 7) & 127;
        int f = i & 127;
        float v = W[i];
        __nv_bfloat16 hb = __float2bfloat16(v);
        __nv_bfloat16 lb = __float2bfloat16(v - __bfloat162float(hb));
        int o = ((e * DD + f) << 7) + k;
        d_Wth[o] = hb;
        d_Wtl[o] = lb;
    }
    if (i < EE) atomicAdd(&d_cnt[adj[i]], 1);
}

// ---------------- multi-block scan: stage 1 ----------------
__global__ void blockscan_kernel() {
    __shared__ int wsum[8];
    int blk = blockIdx.x, t = threadIdx.x, lane = t & 31, w = t >> 5;
    int i = blk * 256 + t;
    int v = (i < NN) ? d_cnt[i] : 0;
    int s = v;
#pragma unroll
    for (int o = 1; o < 32; o <<= 1) {
        int y = __shfl_up_sync(0xffffffffu, s, o);
        if (lane >= o) s += y;
    }
    if (lane == 31) wsum[w] = s;
    __syncthreads();
    if (t == 0) {
        int acc = 0;
#pragma unroll
        for (int j = 0; j < 8; j++) { int x = wsum[j]; wsum[j] = acc; acc += x; }
        d_bsum[blk] = acc;
    }
    __syncthreads();
    if (i < NN) d_off[i] = wsum[w] + s - v;
}

// ---------------- scan stage 2: per-block prefix + add ----------------
__global__ void addoff_kernel() {
    __shared__ int wsum[8];
    __shared__ int s_boff;
    int t = threadIdx.x, lane = t & 31, w = t >> 5;
    int blk = blockIdx.x;
    int v = (t < blk) ? d_bsum[t] : 0;    // NBLK=196 <= 256
#pragma unroll
    for (int o = 16; o > 0; o >>= 1) v += __shfl_xor_sync(0xffffffffu, v, o);
    if (lane == 0) wsum[w] = v;
    __syncthreads();
    if (t == 0) {
        int acc = 0;
#pragma unroll
        for (int j = 0; j < 8; j++) acc += wsum[j];
        s_boff = acc;
    }
    __syncthreads();
    int i = blk * 256 + t;
    if (i < NN) {
        int o = d_off[i] + s_boff;
        d_off[i] = o;
        d_cur[i] = o;
    }
    if (i == 0) d_off[NN] = EE;
}

// ---------------- fused GEMM (bf16x3 mma + ldmatrix, fused s + max) ∪ scatter ----------------
__global__ void __launch_bounds__(256, 2) gemm_scatter_kernel(const float* __restrict__ a,
                                                              const int* __restrict__ adj) {
    int bid = blockIdx.x;
    int t = threadIdx.x;

    if (bid >= GEMM_BLKS) {
        // ---------- scatter path ----------
        int i = (bid - GEMM_BLKS) * 256 + t;
        if (i < EE) {
            int s = adj[i];
            int d = adj[EE + i];
            int p = atomicAdd(&d_cur[s], 1);
            d_csr[p] = d;
        }
        return;
    }

    // ---------- gemm path ----------
    extern __shared__ uint32_t sm[];
    uint32_t smb = (uint32_t)__cvta_generic_to_shared(sm);
    int lane = t & 31, wid = t >> 5;
    int e = bid & 3;
    int n0 = (bid >> 2) * 128;

    float* s1r = (float*)(sm + SRED_W);
    float* s2r = s1r + 128;
    if (t < 128) { s1r[t] = 0.f; s2r[t] = 0.f; }

    int warpM = (wid >> 1) * 32;
    int warpN = (wid & 1) * 64;
    int g = lane >> 2, th = lane & 3;
    int lrow = lane & 15, lhalf = lane >> 4;

    uint32_t aab = smb + (uint32_t)(AH_W + (warpM + lrow) * ROWW + lhalf * 4) * 4;
    uint32_t bab = smb + (uint32_t)(BH_W + (warpN + lrow) * ROWW + lhalf * 4) * 4;

    float acc[2][8][4];
#pragma unroll
    for (int mt = 0; mt < 2; mt++)
#pragma unroll
        for (int nt = 0; nt < 8; nt++)
#pragma unroll
            for (int j = 0; j < 4; j++) acc[mt][nt][j] = 0.f;

    const uint2* xh2 = (const uint2*)d_xh;
    const uint2* xl2 = (const uint2*)d_xl;
    const uint2* wh2 = (const uint2*)(d_Wth + e * DD * DD);
    const uint2* wl2 = (const uint2*)(d_Wtl + e * DD * DD);

#pragma unroll
    for (int s = 0; s < 2; s++) {
        if (s) __syncthreads();

#pragma unroll
        for (int i = 0; i < 8; i++) {
            int q = i * 256 + t;
            int row = q >> 4;
            int kq = q & 15;
            int n = n0 + row;
            uint2 hv = make_uint2(0u, 0u), lv = make_uint2(0u, 0u);
            if (n < NN) {
                hv = xh2[n * 32 + s * 16 + kq];
                lv = xl2[n * 32 + s * 16 + kq];
            }
            *(uint2*)(sm + AH_W + row * ROWW + 2 * kq) = hv;
            *(uint2*)(sm + AL_W + row * ROWW + 2 * kq) = lv;
        }
#pragma unroll
        for (int i = 0; i < 8; i++) {
            int q = i * 256 + t;
            int row = q >> 4;
            int kq = q & 15;
            *(uint2*)(sm + BH_W + row * ROWW + 2 * kq) = wh2[row * 32 + s * 16 + kq];
            *(uint2*)(sm + BL_W + row * ROWW + 2 * kq) = wl2[row * 32 + s * 16 + kq];
        }
        __syncthreads();

#pragma unroll
        for (int kk = 0; kk < 4; kk++) {
            uint32_t kb = kk * 32;
            uint32_t ah[2][4], al[2][4], bh[4][4], bl[4][4];
            ldsm_x4(ah[0], aab + kb);
            ldsm_x4(ah[1], aab + MT_STRIDE_B + kb);
            ldsm_x4(al[0], aab + LO_OFF_B + kb);
            ldsm_x4(al[1], aab + LO_OFF_B + MT_STRIDE_B + kb);
#pragma unroll
            for (int q = 0; q < 4; q++) {
                ldsm_x4(bh[q], bab + q * MT_STRIDE_B + kb);
                ldsm_x4(bl[q], bab + LO_OFF_B + q * MT_STRIDE_B + kb);
            }
#pragma unroll
            for (int nt = 0; nt < 8; nt++) {
                int p = nt >> 1, sl = nt & 1;
                uint32_t b0h = bh[p][sl], b1h = bh[p][2 + sl];
                uint32_t b0l = bl[p][sl], b1l = bl[p][2 + sl];
#pragma unroll
                for (int mt = 0; mt < 2; mt++) {
                    mma_bf16(acc[mt][nt][0], acc[mt][nt][1], acc[mt][nt][2], acc[mt][nt][3],
                             ah[mt][0], ah[mt][1], ah[mt][2], ah[mt][3], b0h, b1h);
                    mma_bf16(acc[mt][nt][0], acc[mt][nt][1], acc[mt][nt][2], acc[mt][nt][3],
                             ah[mt][0], ah[mt][1], ah[mt][2], ah[mt][3], b0l, b1l);
                    mma_bf16(acc[mt][nt][0], acc[mt][nt][1], acc[mt][nt][2], acc[mt][nt][3],
                             al[mt][0], al[mt][1], al[mt][2], al[mt][3], b0h, b1h);
                }
            }
        }
    }

    const float* a1 = a + e * 2 * DD;
    const float* a2 = a1 + DD;
#pragma unroll
    for (int mt = 0; mt < 2; mt++) {
#pragma unroll
        for (int half = 0; half < 2; half++) {
            int row_local = warpM + mt * 16 + half * 8 + g;
            int n = n0 + row_local;
            float p1 = 0.f, p2 = 0.f;
#pragma unroll
            for (int nt = 0; nt < 8; nt++) {
                int col = warpN + nt * 8 + 2 * th;
                float c0 = acc[mt][nt][half * 2];
                float c1 = acc[mt][nt][half * 2 + 1];
                p1 += c0 * __ldg(a1 + col) + c1 * __ldg(a1 + col + 1);
                p2 += c0 * __ldg(a2 + col) + c1 * __ldg(a2 + col + 1);
                if (n < NN)
                    *(__half2*)&d_hh[((size_t)n * NEV + e) * DD + col] = __floats2half2_rn(c0, c1);
            }
            p1 += __shfl_xor_sync(0xffffffffu, p1, 1);
            p1 += __shfl_xor_sync(0xffffffffu, p1, 2);
            p2 += __shfl_xor_sync(0xffffffffu, p2, 1);
            p2 += __shfl_xor_sync(0xffffffffu, p2, 2);
            if (th == 0) {
                atomicAdd(&s1r[row_local], p1);   // exactly 2 adds/addr -> deterministic
                atomicAdd(&s2r[row_local], p2);
            }
        }
    }
    __syncthreads();
    if (t < 128) {
        int n = n0 + t;
        float v1 = s1r[t], v2 = s2r[t];
        bool ok = (n < NN);
        if (ok) {
            d_ssrc[n * NEV + e] = v1;
            d_sdst[n * NEV + e] = v2;
        } else {
            v1 = -1e30f; v2 = -1e30f;
        }
#pragma unroll
        for (int o = 16; o > 0; o >>= 1) {
            v1 = fmaxf(v1, __shfl_xor_sync(0xffffffffu, v1, o));
            v2 = fmaxf(v2, __shfl_xor_sync(0xffffffffu, v2, o));
        }
        if (lane == 0) {
            atomicMax(&d_max1u[e], fenc(v1));
            atomicMax(&d_max2u[e], fenc(v2));
        }
    }
}

// ---------------- aggregate v2: one warp per node, uint4 loads (2 per edge) ----------------
// lane -> (env-pair half, f-chunk): hi = lane>>4, fb = (lane&15)*8 halves.
// round 0 covers envs {0,1} (bytes [0,512) of the node's 1KB), round 1 envs {2,3}.
// lane accumulates env er0 = hi (round 0) and er1 = 2+hi (round 1), 8 features each.
__global__ void agg_kernel(const float* __restrict__ x,
                           const float* __restrict__ envw,
                           float* __restrict__ out) {
    int wid  = (blockIdx.x * blockDim.x + threadIdx.x) >> 5;
    int lane = threadIdx.x & 31;
    if (wid >= NN) return;
    int n = wid;
    int hi = lane >> 4;
    int er0 = hi, er1 = 2 + hi;

    float m[NEV], ss[NEV];
#pragma unroll
    for (int e = 0; e < NEV; e++) {
        // softmax bound: m >= true max logit; exact value cancels in num/denom
        m[e]  = lrelu(fdec(d_max1u[e]) + fdec(d_max2u[e]));
        ss[e] = d_ssrc[n * NEV + e];
    }
    float4 sdn = *(const float4*)&d_sdst[n * NEV];
    float sdv[NEV] = {sdn.x, sdn.y, sdn.z, sdn.w};

    // self loop weights for this lane's two envs
    float w0 = __expf(lrelu(ss[er0] + sdv[er0]) - m[er0]);
    float w1 = __expf(lrelu(ss[er1] + sdv[er1]) - m[er1]);
    float den0 = w0, den1 = w1;

    float acc0[8], acc1[8];
    {
        const char* hp = (const char*)d_hh + (size_t)n * 1024 + lane * 16;
        uint4 u0 = *(const uint4*)hp;
        uint4 u1 = *(const uint4*)(hp + 512);
        float f0[8], f1[8];
        unpack8(u0, f0); unpack8(u1, f1);
#pragma unroll
        for (int k = 0; k < 8; k++) { acc0[k] = w0 * f0[k]; acc1[k] = w1 * f1[k]; }
    }

    int start = d_off[n], end = d_off[n + 1];
    int e_l = lane & 3, j_l = lane >> 2;
    float ss_l = ss[e_l], m_l = m[e_l];

    for (int base = start; base < end; base += 8) {
        int idx = base + j_l;
        int dl = 0;
        float wl = 0.f;
        if (idx < end) {
            dl = d_csr[idx];
            float sv = d_sdst[dl * NEV + e_l];
            wl = __expf(lrelu(ss_l + sv) - m_l);
        }
        int cnt = end - base; if (cnt > 8) cnt = 8;
#pragma unroll
        for (int j = 0; j < 8; j++) {
            if (j >= cnt) break;
            int d = __shfl_sync(0xffffffffu, dl, j * 4);
            float we0 = __shfl_sync(0xffffffffu, wl, j * 4 + er0);
            float we1 = __shfl_sync(0xffffffffu, wl, j * 4 + er1);
            const char* hp = (const char*)d_hh + (size_t)d * 1024 + lane * 16;
            uint4 u0 = *(const uint4*)hp;
            uint4 u1 = *(const uint4*)(hp + 512);
            float f0[8], f1[8];
            unpack8(u0, f0); unpack8(u1, f1);
            den0 += we0; den1 += we1;
#pragma unroll
            for (int k = 0; k < 8; k++) {
                acc0[k] += we0 * f0[k];
                acc1[k] += we1 * f1[k];
            }
        }
    }

    float4 ew = *(const float4*)&envw[n * NEV];
    float c0 = ((hi == 0) ? ew.x : ew.y) / (den0 + EPSV);
    float c1 = ((hi == 0) ? ew.z : ew.w) / (den1 + EPSV);
    float tot[8];
#pragma unroll
    for (int k = 0; k < 8; k++) tot[k] = c0 * acc0[k] + c1 * acc1[k];
#pragma unroll
    for (int k = 0; k < 8; k++) tot[k] += __shfl_xor_sync(0xffffffffu, tot[k], 16);

    // store: lane writes float4 at f = (lane&15)*8 + hi*4 (32 lanes cover 128 floats)
    int fi = (lane & 15) * 8 + hi * 4;
    float4 xv = *(const float4*)&x[(size_t)n * DD + fi];
    float4 o;
    o.x = xv.x + tot[hi * 4 + 0];
    o.y = xv.y + tot[hi * 4 + 1];
    o.z = xv.z + tot[hi * 4 + 2];
    o.w = xv.w + tot[hi * 4 + 3];
    *(float4*)&out[(size_t)n * DD + fi] = o;
}

// ---------------- launcher ----------------
extern "C" void kernel_launch(void* const* d_in, const int* in_sizes, int n_in,
                              void* d_out, int out_size) {
    const float* x    = (const float*)d_in[0];
    const int*   adj  = (const int*)d_in[1];
    const float* envw = (const float*)d_in[2];
    const float* W    = (const float*)d_in[3];
    const float* a    = (const float*)d_in[4];
    float* out = (float*)d_out;

    cudaFuncSetAttribute(gemm_scatter_kernel, cudaFuncAttributeMaxDynamicSharedMemorySize, SMEM_BYTES);

    zinit_kernel<<<NBLK, 256>>>();
    prep_kernel<<<(NN * 32 + 255) / 256, 256>>>(x, W, adj);
    blockscan_kernel<<<NBLK, 256>>>();
    addoff_kernel<<<NBLK, 256>>>();
    gemm_scatter_kernel<<<GEMM_BLKS + SCAT_BLKS, 256, SMEM_BYTES>>>(a, adj);
    agg_kernel<<<(NN + 7) / 8, 256>>>(x, envw, out);
}